// round 1
// baseline (speedup 1.0000x reference)
#include <cuda_runtime.h>
#include <cuda_bf16.h>
#include <cstdint>

// ---------------------------------------------------------------------------
// Net_46368466928157: sparse autoencoder forward
//   h = relu(x @ W1^T + b1)            [16384,1024]
//   c = relu(h @ W2^T + b2)            [16384,2048]
//   c *= topk_mask(c, 64)              per-row neuron top-64
//   stripes: 32 x 64; stripe mean -> top-4 stripes -> mask
//   d = relu(c @ W3^T + b3)            [16384,1024]
//   out = relu(d @ W4^T + b4)          [16384,784]
// ---------------------------------------------------------------------------

#define BATCH 16384
#define IN_DIM 784
#define INTER 1024
#define CODE 2048
#define NSTRIPE 32
#define SDIM 64
#define KNEUR 64
#define KSTRIPE 4

// Scratch (allocation-free rule: __device__ globals)
__device__ float g_h[(size_t)BATCH * INTER];
__device__ float g_c[(size_t)BATCH * CODE];
__device__ float g_d[(size_t)BATCH * INTER];

// ---------------------------------------------------------------------------
// SGEMM: C[m,n] = relu(bias[n] + sum_k A[m,k] * B[n,k])
// A: [M,K] row-major, B: [N,K] row-major (weights as given), C: [M,N]
// BM=BN=128, BK=16, 256 threads, 8x8 per thread (split 4+4).
// Requires: K % 16 == 0, M % 128 == 0, N % 4 == 0. (All hold here.)
// ---------------------------------------------------------------------------
__global__ __launch_bounds__(256) void sgemm_bias_relu(
    const float* __restrict__ A, const float* __restrict__ B,
    const float* __restrict__ bias, float* __restrict__ C,
    int M, int N, int K)
{
    const int BM = 128, BN = 128, BK = 16;
    __shared__ float As[BK][BM + 4];
    __shared__ float Bs[BK][BN + 4];

    const int tid = threadIdx.x;
    const int tx = tid & 15;   // n direction (16)
    const int ty = tid >> 4;   // m direction (16)
    const int bm = blockIdx.y * BM;
    const int bn = blockIdx.x * BN;

    const float* Aptr = A + (size_t)bm * K;
    const float* Bptr = B + (size_t)bn * K;

    float acc[8][8];
#pragma unroll
    for (int i = 0; i < 8; i++)
#pragma unroll
        for (int j = 0; j < 8; j++) acc[i][j] = 0.0f;

    for (int k0 = 0; k0 < K; k0 += BK) {
        // Load A tile: 128 rows x 16 k -> 512 float4, 2 per thread
#pragma unroll
        for (int i = 0; i < 2; i++) {
            int f = tid * 2 + i;
            int row = f >> 2;
            int k4 = (f & 3) * 4;
            float4 v = *(const float4*)(Aptr + (size_t)row * K + k0 + k4);
            As[k4 + 0][row] = v.x;
            As[k4 + 1][row] = v.y;
            As[k4 + 2][row] = v.z;
            As[k4 + 3][row] = v.w;
        }
        // Load B tile (guard n-rows beyond N with zeros)
#pragma unroll
        for (int i = 0; i < 2; i++) {
            int f = tid * 2 + i;
            int row = f >> 2;
            int k4 = (f & 3) * 4;
            float4 v = make_float4(0.f, 0.f, 0.f, 0.f);
            if (bn + row < N)
                v = *(const float4*)(Bptr + (size_t)row * K + k0 + k4);
            Bs[k4 + 0][row] = v.x;
            Bs[k4 + 1][row] = v.y;
            Bs[k4 + 2][row] = v.z;
            Bs[k4 + 3][row] = v.w;
        }
        __syncthreads();

#pragma unroll
        for (int k = 0; k < BK; k++) {
            float a[8], b[8];
            *(float4*)&a[0] = *(const float4*)&As[k][ty * 4];
            *(float4*)&a[4] = *(const float4*)&As[k][64 + ty * 4];
            *(float4*)&b[0] = *(const float4*)&Bs[k][tx * 4];
            *(float4*)&b[4] = *(const float4*)&Bs[k][64 + tx * 4];
#pragma unroll
            for (int i = 0; i < 8; i++)
#pragma unroll
                for (int j = 0; j < 8; j++)
                    acc[i][j] = fmaf(a[i], b[j], acc[i][j]);
        }
        __syncthreads();
    }

    // Epilogue: bias + relu, float4 stores, guard n < N
#pragma unroll
    for (int im = 0; im < 8; im++) {
        int m = bm + (im < 4 ? ty * 4 + im : 64 + ty * 4 + (im - 4));
        float* crow = C + (size_t)m * N;
#pragma unroll
        for (int jh = 0; jh < 2; jh++) {
            int n = bn + (jh == 0 ? tx * 4 : 64 + tx * 4);
            if (n < N) {
                float4 bv = *(const float4*)&bias[n];
                float4 r;
                r.x = fmaxf(acc[im][jh * 4 + 0] + bv.x, 0.0f);
                r.y = fmaxf(acc[im][jh * 4 + 1] + bv.y, 0.0f);
                r.z = fmaxf(acc[im][jh * 4 + 2] + bv.z, 0.0f);
                r.w = fmaxf(acc[im][jh * 4 + 3] + bv.w, 0.0f);
                *(float4*)&crow[n] = r;
            }
        }
    }
}

// ---------------------------------------------------------------------------
// Fused per-row top-k: exact neuron top-64 (radix select over uint bits of
// nonneg floats, index-ordered tie-break like jax.lax.top_k), then stripe
// sums (32 stripes of 64) and top-4 stripe select. In-place on c.
// One block (256 threads) per row; each thread owns 8 contiguous elements.
// ---------------------------------------------------------------------------
__global__ __launch_bounds__(256) void topk_mask_kernel(float* __restrict__ C)
{
    const int tid = threadIdx.x;
    float* crow = C + (size_t)blockIdx.x * CODE;

    __shared__ unsigned int hist[256];
    __shared__ unsigned int eqscan[257];
    __shared__ float psum[256];
    __shared__ float ssum[NSTRIPE];
    __shared__ float smask[NSTRIPE];
    __shared__ unsigned int s_prefix;
    __shared__ unsigned int s_remk;

    // Load 8 contiguous elements per thread (index order = global order)
    float f[8];
    *(float4*)&f[0] = *(const float4*)(crow + tid * 8);
    *(float4*)&f[4] = *(const float4*)(crow + tid * 8 + 4);
    unsigned int u[8];
#pragma unroll
    for (int j = 0; j < 8; j++) u[j] = __float_as_uint(f[j]);  // nonneg: uint order == float order

    if (tid == 0) { s_prefix = 0; s_remk = KNEUR; }
    __syncthreads();

    // 4-pass 8-bit radix select for the 64th-largest value
#pragma unroll
    for (int pass = 0; pass < 4; pass++) {
        const int shift = 24 - pass * 8;
        const unsigned int pm = (pass == 0) ? 0u : (0xFFFFFFFFu << (shift + 8));
        hist[tid] = 0;
        __syncthreads();
        unsigned int pref = s_prefix;
#pragma unroll
        for (int j = 0; j < 8; j++) {
            if ((u[j] & pm) == pref)
                atomicAdd(&hist[(u[j] >> shift) & 0xFF], 1u);
        }
        __syncthreads();
        if (tid == 0) {
            unsigned int remk = s_remk, acc = 0;
            int b = 255;
            for (; b > 0; b--) {
                acc += hist[b];
                if (acc >= remk) break;
            }
            if (acc < remk) acc += hist[0];  // b == 0 fallthrough
            s_prefix = pref | ((unsigned int)b << shift);
            s_remk = remk - (acc - hist[b]);
        }
        __syncthreads();
    }

    const unsigned int t = s_prefix;        // bit pattern of 64th largest
    const unsigned int need_eq = s_remk;    // how many ==t to keep (index order)

    // Exclusive scan of per-thread equal-counts (global index order)
    unsigned int cnt = 0;
#pragma unroll
    for (int j = 0; j < 8; j++) cnt += (u[j] == t);
    eqscan[tid] = cnt;
    __syncthreads();
    if (tid == 0) {
        unsigned int run = 0;
        for (int i = 0; i < 256; i++) {
            unsigned int v = eqscan[i];
            eqscan[i] = run;
            run += v;
        }
    }
    __syncthreads();

    // Apply neuron mask; accumulate stripe partial (thread's 8 elems all in stripe tid/8)
    unsigned int rank = eqscan[tid];
    float part = 0.0f;
#pragma unroll
    for (int j = 0; j < 8; j++) {
        bool keep;
        if (u[j] > t) keep = true;
        else if (u[j] == t) { keep = (rank < need_eq); rank++; }
        else keep = false;
        if (!keep) f[j] = 0.0f;
        part += f[j];
    }
    psum[tid] = part;
    __syncthreads();

    // Stripe sums: 8 threads per stripe
    if (tid < NSTRIPE) {
        float s = 0.0f;
#pragma unroll
        for (int i = 0; i < 8; i++) s += psum[tid * 8 + i];
        ssum[tid] = s;   // sum is monotone with mean; topk identical
    }
    __syncthreads();

    // Top-4 stripe select with lowest-index tie-break (strict > keeps first)
    if (tid == 0) {
        bool sel[NSTRIPE];
#pragma unroll
        for (int s = 0; s < NSTRIPE; s++) sel[s] = false;
        for (int it = 0; it < KSTRIPE; it++) {
            int best = -1;
            float bv = -1.0f;
            for (int s = 0; s < NSTRIPE; s++) {
                if (!sel[s] && ssum[s] > bv) { bv = ssum[s]; best = s; }
            }
            sel[best] = true;
        }
#pragma unroll
        for (int s = 0; s < NSTRIPE; s++) smask[s] = sel[s] ? 1.0f : 0.0f;
    }
    __syncthreads();

    const float sm = smask[tid >> 3];
#pragma unroll
    for (int j = 0; j < 8; j++) f[j] *= sm;
    *(float4*)(crow + tid * 8) = *(float4*)&f[0];
    *(float4*)(crow + tid * 8 + 4) = *(float4*)&f[4];
}

// ---------------------------------------------------------------------------
extern "C" void kernel_launch(void* const* d_in, const int* in_sizes, int n_in,
                              void* d_out, int out_size)
{
    const float* x  = (const float*)d_in[0];
    const float* W1 = (const float*)d_in[1];
    const float* b1 = (const float*)d_in[2];
    const float* W2 = (const float*)d_in[3];
    const float* b2 = (const float*)d_in[4];
    const float* W3 = (const float*)d_in[5];
    const float* b3 = (const float*)d_in[6];
    const float* W4 = (const float*)d_in[7];
    const float* b4 = (const float*)d_in[8];
    float* out = (float*)d_out;

    float *h, *c, *d;
    cudaGetSymbolAddress((void**)&h, g_h);
    cudaGetSymbolAddress((void**)&c, g_c);
    cudaGetSymbolAddress((void**)&d, g_d);

    dim3 blk(256);
    // Layer 1: [16384,784] x [1024,784]^T -> [16384,1024]
    sgemm_bias_relu<<<dim3(INTER / 128, BATCH / 128), blk>>>(x, W1, b1, h, BATCH, INTER, IN_DIM);
    // Layer 2: -> [16384,2048]
    sgemm_bias_relu<<<dim3(CODE / 128, BATCH / 128), blk>>>(h, W2, b2, c, BATCH, CODE, INTER);
    // Sparsity: neuron top-64 + stripe top-4 (in place)
    topk_mask_kernel<<<BATCH, 256>>>(c);
    // Layer 3: -> [16384,1024]
    sgemm_bias_relu<<<dim3(INTER / 128, BATCH / 128), blk>>>(c, W3, b3, d, BATCH, INTER, CODE);
    // Layer 4: -> [16384,784]
    sgemm_bias_relu<<<dim3((IN_DIM + 127) / 128, BATCH / 128), blk>>>(d, W4, b4, out, BATCH, IN_DIM, INTER);
}

// round 7
// speedup vs baseline: 1.3112x; 1.3112x over previous
#include <cuda_runtime.h>
#include <cuda_bf16.h>
#include <cstdint>

// ---------------------------------------------------------------------------
// Net_46368466928157 — hybrid:
//   L1,L2 (feeding top-k): R1's fp32 FFMA SGEMM, bit-identical to the passing
//     baseline -> identical top-k selections (zero flips by construction).
//   L3,L4 (after masking):  HMMA bf16 2-part split (3 terms), ~1e-5 accuracy.
// ---------------------------------------------------------------------------

#define BATCH   16384
#define IN_DIM  784
#define INTER   1024
#define CODE    2048
#define N4P     896
#define NSTRIPE 32
#define KNEUR   64
#define KSTRIPE 4

typedef __nv_bfloat16 bf16;

// ---- scratch --------------------------------------------------------------
__device__ float g_h[(size_t)BATCH * INTER];
__device__ float g_c[(size_t)BATCH * CODE];
__device__ bf16  g_c0[(size_t)BATCH * CODE],  g_c1[(size_t)BATCH * CODE];
__device__ bf16  g_w3_0[(size_t)INTER * CODE], g_w3_1[(size_t)INTER * CODE];
__device__ bf16  g_d0[(size_t)BATCH * INTER],  g_d1[(size_t)BATCH * INTER];
__device__ bf16  g_w4_0[(size_t)N4P * INTER],  g_w4_1[(size_t)N4P * INTER];

// ===========================================================================
// R1 fp32 SGEMM (verbatim): C = relu(bias + A @ B^T)
// ===========================================================================
__global__ __launch_bounds__(256) void sgemm_bias_relu(
    const float* __restrict__ A, const float* __restrict__ B,
    const float* __restrict__ bias, float* __restrict__ C,
    int M, int N, int K)
{
    const int BM = 128, BN = 128, BK = 16;
    __shared__ float As[BK][BM + 4];
    __shared__ float Bs[BK][BN + 4];

    const int tid = threadIdx.x;
    const int tx = tid & 15;
    const int ty = tid >> 4;
    const int bm = blockIdx.y * BM;
    const int bn = blockIdx.x * BN;

    const float* Aptr = A + (size_t)bm * K;
    const float* Bptr = B + (size_t)bn * K;

    float acc[8][8];
#pragma unroll
    for (int i = 0; i < 8; i++)
#pragma unroll
        for (int j = 0; j < 8; j++) acc[i][j] = 0.0f;

    for (int k0 = 0; k0 < K; k0 += BK) {
#pragma unroll
        for (int i = 0; i < 2; i++) {
            int f = tid * 2 + i;
            int row = f >> 2;
            int k4 = (f & 3) * 4;
            float4 v = *(const float4*)(Aptr + (size_t)row * K + k0 + k4);
            As[k4 + 0][row] = v.x;
            As[k4 + 1][row] = v.y;
            As[k4 + 2][row] = v.z;
            As[k4 + 3][row] = v.w;
        }
#pragma unroll
        for (int i = 0; i < 2; i++) {
            int f = tid * 2 + i;
            int row = f >> 2;
            int k4 = (f & 3) * 4;
            float4 v = make_float4(0.f, 0.f, 0.f, 0.f);
            if (bn + row < N)
                v = *(const float4*)(Bptr + (size_t)row * K + k0 + k4);
            Bs[k4 + 0][row] = v.x;
            Bs[k4 + 1][row] = v.y;
            Bs[k4 + 2][row] = v.z;
            Bs[k4 + 3][row] = v.w;
        }
        __syncthreads();

#pragma unroll
        for (int k = 0; k < BK; k++) {
            float a[8], b[8];
            *(float4*)&a[0] = *(const float4*)&As[k][ty * 4];
            *(float4*)&a[4] = *(const float4*)&As[k][64 + ty * 4];
            *(float4*)&b[0] = *(const float4*)&Bs[k][tx * 4];
            *(float4*)&b[4] = *(const float4*)&Bs[k][64 + tx * 4];
#pragma unroll
            for (int i = 0; i < 8; i++)
#pragma unroll
                for (int j = 0; j < 8; j++)
                    acc[i][j] = fmaf(a[i], b[j], acc[i][j]);
        }
        __syncthreads();
    }

#pragma unroll
    for (int im = 0; im < 8; im++) {
        int m = bm + (im < 4 ? ty * 4 + im : 64 + ty * 4 + (im - 4));
        float* crow = C + (size_t)m * N;
#pragma unroll
        for (int jh = 0; jh < 2; jh++) {
            int n = bn + (jh == 0 ? tx * 4 : 64 + tx * 4);
            if (n < N) {
                float4 bv = *(const float4*)&bias[n];
                float4 r;
                r.x = fmaxf(acc[im][jh * 4 + 0] + bv.x, 0.0f);
                r.y = fmaxf(acc[im][jh * 4 + 1] + bv.y, 0.0f);
                r.z = fmaxf(acc[im][jh * 4 + 2] + bv.z, 0.0f);
                r.w = fmaxf(acc[im][jh * 4 + 3] + bv.w, 0.0f);
                *(float4*)&crow[n] = r;
            }
        }
    }
}

// ===========================================================================
// HMMA split GEMM (L3/L4): PREC=2 parts, 3 terms.
// ===========================================================================
__device__ __forceinline__ uint32_t smem_u32(const void* p) {
    uint32_t a;
    asm("{ .reg .u64 t; cvta.to.shared.u64 t, %1; cvt.u32.u64 %0, t; }" : "=r"(a) : "l"(p));
    return a;
}
#define CP_ASYNC16(dst, src) \
    asm volatile("cp.async.cg.shared.global [%0], [%1], 16;" :: "r"(dst), "l"(src) : "memory")
#define CP_COMMIT()  asm volatile("cp.async.commit_group;" ::: "memory")
#define CP_WAIT(n)   asm volatile("cp.async.wait_group %0;" :: "n"(n) : "memory")

__device__ __forceinline__ void ldsm_x4(uint32_t& r0, uint32_t& r1, uint32_t& r2,
                                        uint32_t& r3, uint32_t addr) {
    asm volatile("ldmatrix.sync.aligned.m8n8.x4.shared.b16 {%0,%1,%2,%3}, [%4];"
        : "=r"(r0), "=r"(r1), "=r"(r2), "=r"(r3) : "r"(addr));
}
__device__ __forceinline__ void mma16816(float* c, const uint32_t* a, const uint32_t* b) {
    asm volatile("mma.sync.aligned.m16n8k16.row.col.f32.bf16.bf16.f32 "
        "{%0,%1,%2,%3}, {%4,%5,%6,%7}, {%8,%9}, {%0,%1,%2,%3};"
        : "+f"(c[0]), "+f"(c[1]), "+f"(c[2]), "+f"(c[3])
        : "r"(a[0]), "r"(a[1]), "r"(a[2]), "r"(a[3]), "r"(b[0]), "r"(b[1]));
}

#define ROWB   80
#define TILE_B (128 * ROWB)
#define SM_TILES 1024
#define SMEM_HMMA (SM_TILES + 2 * 4 * TILE_B)   // PREC=2: 4 tiles/stage

// MODE 0: fp32 out (guard n<Nvalid). MODE 1: 2-part bf16 out.
template<int MODE>
__global__ __launch_bounds__(256, 1) void gemm_split2(
    const bf16* __restrict__ A0, const bf16* __restrict__ A1,
    const bf16* __restrict__ B0, const bf16* __restrict__ B1,
    const float* __restrict__ bias,
    float* __restrict__ Cf, bf16* __restrict__ C0, bf16* __restrict__ C1,
    int Kp, int Nvalid, int outStride)
{
    extern __shared__ char smem[];
    const uint32_t sbase = smem_u32(smem) + SM_TILES;
    const int tid  = threadIdx.x;
    const int warp = tid >> 5, lane = tid & 31;
    const int wm = (warp >> 2) * 64;
    const int wn = (warp & 3) * 32;
    const int m0 = blockIdx.y * 128;
    const int n0 = blockIdx.x * 128;

    if (tid < 128) {
        int n = n0 + tid;
        ((float*)smem)[tid] = (n < Nvalid) ? bias[n] : 0.0f;
    }

    float acc[4][4][4];
#pragma unroll
    for (int i = 0; i < 4; i++)
#pragma unroll
        for (int j = 0; j < 4; j++)
#pragma unroll
            for (int q = 0; q < 4; q++) acc[i][j][q] = 0.0f;

    const bf16* Ap[2] = { A0, A1 };
    const bf16* Bp[2] = { B0, B1 };
    const int nk = Kp / 32;

    auto load_stage = [&](int kc, int s) {
        const int k0 = kc * 32;
        const uint32_t stb = sbase + s * 4 * TILE_B;
#pragma unroll
        for (int t = 0; t < 4; t++) {
            const bf16* base = (t < 2) ? (Ap[t] + (size_t)m0 * Kp)
                                       : (Bp[t - 2] + (size_t)n0 * Kp);
#pragma unroll
            for (int i = 0; i < 2; i++) {
                int f = tid + i * 256;
                int row = f >> 2, c = f & 3;
                uint32_t dst = stb + t * TILE_B + row * ROWB + c * 16;
                CP_ASYNC16(dst, base + (size_t)row * Kp + k0 + c * 8);
            }
        }
        CP_COMMIT();
    };

    auto compute_stage = [&](int s) {
        const uint32_t stb = sbase + s * 4 * TILE_B;
#pragma unroll
        for (int ks = 0; ks < 2; ks++) {
            uint32_t afr[2][4][4];
#pragma unroll
            for (int p = 0; p < 2; p++) {
                const uint32_t Ab = stb + p * TILE_B;
#pragma unroll
                for (int mf = 0; mf < 4; mf++) {
                    int row = wm + mf * 16 + (lane & 15);
                    uint32_t off = row * ROWB + ks * 32 + (lane >> 4) * 16;
                    ldsm_x4(afr[p][mf][0], afr[p][mf][1], afr[p][mf][2], afr[p][mf][3], Ab + off);
                }
            }
#pragma unroll
            for (int j = 0; j < 2; j++) {
                const uint32_t Bb = stb + (2 + j) * TILE_B;
                uint32_t bfr[4][2];
#pragma unroll
                for (int p = 0; p < 2; p++) {
                    int g = lane >> 3, ri = lane & 7;
                    int row = wn + p * 16 + ((g >> 1) << 3) + ri;
                    uint32_t off = row * ROWB + (2 * ks + (g & 1)) * 16;
                    uint32_t t0, t1, t2, t3;
                    ldsm_x4(t0, t1, t2, t3, Bb + off);
                    bfr[p*2][0] = t0; bfr[p*2][1] = t1;
                    bfr[p*2+1][0] = t2; bfr[p*2+1][1] = t3;
                }
#pragma unroll
                for (int i = 0; i < 2 - j; i++)     // (0,0),(1,0),(0,1)
#pragma unroll
                    for (int mf = 0; mf < 4; mf++)
#pragma unroll
                        for (int nf = 0; nf < 4; nf++)
                            mma16816(acc[mf][nf], afr[i][mf], bfr[nf]);
            }
        }
    };

    load_stage(0, 0);
    for (int kc = 0; kc < nk; kc++) {
        if (kc + 1 < nk) { load_stage(kc + 1, (kc + 1) & 1); CP_WAIT(1); }
        else             { CP_WAIT(0); }
        __syncthreads();
        compute_stage(kc & 1);
        __syncthreads();
    }

    const float* bs = (const float*)smem;
    const int lr = lane >> 2;
    const int lc = (lane & 3) * 2;
#pragma unroll
    for (int mf = 0; mf < 4; mf++) {
#pragma unroll
        for (int nf = 0; nf < 4; nf++) {
            int nrel = wn + nf * 8 + lc;
            int n = n0 + nrel;
            float b0 = bs[nrel], b1 = bs[nrel + 1];
#pragma unroll
            for (int half = 0; half < 2; half++) {
                int m = m0 + wm + mf * 16 + lr + half * 8;
                float v0 = fmaxf(acc[mf][nf][half * 2 + 0] + b0, 0.0f);
                float v1 = fmaxf(acc[mf][nf][half * 2 + 1] + b1, 0.0f);
                if (MODE == 0) {
                    if (n < Nvalid)
                        *(float2*)(Cf + (size_t)m * outStride + n) = make_float2(v0, v1);
                } else {
                    __nv_bfloat162 p0, p1;
                    p0.x = __float2bfloat16(v0);
                    p0.y = __float2bfloat16(v1);
                    p1.x = __float2bfloat16(v0 - __bfloat162float(p0.x));
                    p1.y = __float2bfloat16(v1 - __bfloat162float(p0.y));
                    *(__nv_bfloat162*)(C0 + (size_t)m * outStride + n) = p0;
                    *(__nv_bfloat162*)(C1 + (size_t)m * outStride + n) = p1;
                }
            }
        }
    }
}

// ---------------------------------------------------------------------------
// fp32 -> 2 bf16 parts with zero-padding
// ---------------------------------------------------------------------------
__global__ __launch_bounds__(256) void split_pad2(
    const float* __restrict__ src, bf16* __restrict__ P0, bf16* __restrict__ P1,
    int srows, int scols, int orows, int ocols)
{
    size_t i = (size_t)blockIdx.x * blockDim.x + threadIdx.x;
    size_t tot = (size_t)orows * ocols;
    if (i >= tot) return;
    int r = (int)(i / ocols), c = (int)(i % ocols);
    float v = (r < srows && c < scols) ? src[(size_t)r * scols + c] : 0.0f;
    bf16 a = __float2bfloat16(v);
    P0[i] = a;
    P1[i] = __float2bfloat16(v - __bfloat162float(a));
}

// ---------------------------------------------------------------------------
// top-k (R1 logic, bit-identical selections); emits masked 2-part bf16
// ---------------------------------------------------------------------------
__global__ __launch_bounds__(256) void topk_mask_kernel(
    const float* __restrict__ C, bf16* __restrict__ C0, bf16* __restrict__ C1)
{
    const int tid = threadIdx.x;
    const float* crow = C + (size_t)blockIdx.x * CODE;

    __shared__ unsigned int hist[256];
    __shared__ unsigned int eqscan[256];
    __shared__ float psum[256];
    __shared__ float ssum[NSTRIPE];
    __shared__ float smask[NSTRIPE];
    __shared__ unsigned int s_prefix, s_remk;

    float f[8];
    *(float4*)&f[0] = *(const float4*)(crow + tid * 8);
    *(float4*)&f[4] = *(const float4*)(crow + tid * 8 + 4);
    unsigned int u[8];
#pragma unroll
    for (int j = 0; j < 8; j++) u[j] = __float_as_uint(f[j]);

    if (tid == 0) { s_prefix = 0; s_remk = KNEUR; }
    __syncthreads();

#pragma unroll
    for (int pass = 0; pass < 4; pass++) {
        const int shift = 24 - pass * 8;
        const unsigned int pm = (pass == 0) ? 0u : (0xFFFFFFFFu << (shift + 8));
        hist[tid] = 0;
        __syncthreads();
        unsigned int pref = s_prefix;
#pragma unroll
        for (int j = 0; j < 8; j++)
            if ((u[j] & pm) == pref) atomicAdd(&hist[(u[j] >> shift) & 0xFF], 1u);
        __syncthreads();
        if (tid == 0) {
            unsigned int remk = s_remk, acc = 0;
            int b = 255;
            for (; b > 0; b--) { acc += hist[b]; if (acc >= remk) break; }
            if (acc < remk) acc += hist[0];
            s_prefix = pref | ((unsigned int)b << shift);
            s_remk = remk - (acc - hist[b]);
        }
        __syncthreads();
    }

    const unsigned int t = s_prefix;
    const unsigned int need_eq = s_remk;

    unsigned int cnt = 0;
#pragma unroll
    for (int j = 0; j < 8; j++) cnt += (u[j] == t);
    eqscan[tid] = cnt;
    __syncthreads();
    if (tid == 0) {
        unsigned int run = 0;
        for (int i = 0; i < 256; i++) { unsigned int v = eqscan[i]; eqscan[i] = run; run += v; }
    }
    __syncthreads();

    unsigned int rank = eqscan[tid];
    float part = 0.0f;
#pragma unroll
    for (int j = 0; j < 8; j++) {
        bool keep;
        if (u[j] > t) keep = true;
        else if (u[j] == t) { keep = (rank < need_eq); rank++; }
        else keep = false;
        if (!keep) f[j] = 0.0f;
        part += f[j];
    }
    psum[tid] = part;
    __syncthreads();

    if (tid < NSTRIPE) {
        float s = 0.0f;
#pragma unroll
        for (int i = 0; i < 8; i++) s += psum[tid * 8 + i];
        ssum[tid] = s;
    }
    __syncthreads();

    if (tid == 0) {
        bool sel[NSTRIPE];
#pragma unroll
        for (int s = 0; s < NSTRIPE; s++) sel[s] = false;
        for (int it = 0; it < KSTRIPE; it++) {
            int best = -1; float bv = -1.0f;
            for (int s = 0; s < NSTRIPE; s++)
                if (!sel[s] && ssum[s] > bv) { bv = ssum[s]; best = s; }
            sel[best] = true;
        }
#pragma unroll
        for (int s = 0; s < NSTRIPE; s++) smask[s] = sel[s] ? 1.0f : 0.0f;
    }
    __syncthreads();

    const float sm = smask[tid >> 3];
    bf16* hrow = C0 + (size_t)blockIdx.x * CODE + tid * 8;
    bf16* lrow = C1 + (size_t)blockIdx.x * CODE + tid * 8;
#pragma unroll
    for (int j = 0; j < 8; j += 2) {
        float v0 = f[j] * sm, v1 = f[j+1] * sm;
        __nv_bfloat162 h2, l2;
        h2.x = __float2bfloat16(v0);
        h2.y = __float2bfloat16(v1);
        l2.x = __float2bfloat16(v0 - __bfloat162float(h2.x));
        l2.y = __float2bfloat16(v1 - __bfloat162float(h2.y));
        *(__nv_bfloat162*)&hrow[j] = h2;
        *(__nv_bfloat162*)&lrow[j] = l2;
    }
}

// ---------------------------------------------------------------------------
extern "C" void kernel_launch(void* const* d_in, const int* in_sizes, int n_in,
                              void* d_out, int out_size)
{
    const float* x  = (const float*)d_in[0];
    const float* W1 = (const float*)d_in[1];
    const float* b1 = (const float*)d_in[2];
    const float* W2 = (const float*)d_in[3];
    const float* b2 = (const float*)d_in[4];
    const float* W3 = (const float*)d_in[5];
    const float* b3 = (const float*)d_in[6];
    const float* W4 = (const float*)d_in[7];
    const float* b4 = (const float*)d_in[8];
    float* out = (float*)d_out;

    float *h, *c;
    bf16 *c0, *c1, *w30, *w31, *d0, *d1, *w40, *w41;
    cudaGetSymbolAddress((void**)&h, g_h);
    cudaGetSymbolAddress((void**)&c, g_c);
    cudaGetSymbolAddress((void**)&c0, g_c0);   cudaGetSymbolAddress((void**)&c1, g_c1);
    cudaGetSymbolAddress((void**)&w30, g_w3_0); cudaGetSymbolAddress((void**)&w31, g_w3_1);
    cudaGetSymbolAddress((void**)&d0, g_d0);   cudaGetSymbolAddress((void**)&d1, g_d1);
    cudaGetSymbolAddress((void**)&w40, g_w4_0); cudaGetSymbolAddress((void**)&w41, g_w4_1);

    cudaFuncSetAttribute(gemm_split2<0>, cudaFuncAttributeMaxDynamicSharedMemorySize, SMEM_HMMA);
    cudaFuncSetAttribute(gemm_split2<1>, cudaFuncAttributeMaxDynamicSharedMemorySize, SMEM_HMMA);

    auto gs = [](size_t n) { return (unsigned)((n + 255) / 256); };

    // weight splits for L3/L4 (off critical path, cheap)
    split_pad2<<<gs((size_t)INTER * CODE), 256>>>(W3, w30, w31, INTER, CODE, INTER, CODE);
    split_pad2<<<gs((size_t)N4P * INTER), 256>>>(W4, w40, w41, IN_DIM, INTER, N4P, INTER);

    // L1, L2: fp32 (bit-identical to R1 -> identical top-k decisions)
    sgemm_bias_relu<<<dim3(INTER / 128, BATCH / 128), 256>>>(x, W1, b1, h, BATCH, INTER, IN_DIM);
    sgemm_bias_relu<<<dim3(CODE / 128, BATCH / 128), 256>>>(h, W2, b2, c, BATCH, CODE, INTER);

    // sparsity (exact fp32) -> masked 2-part bf16
    topk_mask_kernel<<<BATCH, 256>>>(c, c0, c1);

    // L3: HMMA split -> d pair
    gemm_split2<1><<<dim3(INTER / 128, BATCH / 128), 256, SMEM_HMMA>>>(
        c0, c1, w30, w31, b3, nullptr, d0, d1, CODE, INTER, INTER);
    // L4: HMMA split -> out fp32
    gemm_split2<0><<<dim3(N4P / 128, BATCH / 128), 256, SMEM_HMMA>>>(
        d0, d1, w40, w41, b4, out, nullptr, nullptr, INTER, IN_DIM, IN_DIM);
}

// round 8
// speedup vs baseline: 1.3286x; 1.0133x over previous
#include <cuda_runtime.h>
#include <cuda_bf16.h>
#include <cuda_fp16.h>
#include <cstdint>

// ---------------------------------------------------------------------------
// Net_46368466928157 — round 8:
//   L1: R1 fp32 SGEMM (bit-anchor for h)
//   L2: fp16 scaled 2-part split HMMA (dual accumulators) -> c~ (~2e-6 error)
//   topk: computes boundary gaps; rows with gap < tau get EXACT recompute
//         (serial fmaf chain == R1 bits) + exact re-selection  -> zero flips
//   L3/L4: validated bf16 2-part HMMA split
// ---------------------------------------------------------------------------

#define BATCH   16384
#define IN_DIM  784
#define INTER   1024
#define CODE    2048
#define N4P     896
#define NSTRIPE 32
#define KNEUR   64
#define KSTRIPE 4

#define TAU1 2e-5f     // neuron 64/65 gap margin
#define TAU2 2e-3f     // stripe 4/5 gap margin

typedef __nv_bfloat16 bf16;

// ---- scratch --------------------------------------------------------------
__device__ float  g_h[(size_t)BATCH * INTER];
__device__ float  g_c[(size_t)BATCH * CODE];
__device__ __half g_hh16[(size_t)BATCH * INTER], g_hl16[(size_t)BATCH * INTER];
__device__ __half g_w2h16[(size_t)CODE * INTER], g_w2l16[(size_t)CODE * INTER];
__device__ bf16   g_c0[(size_t)BATCH * CODE],  g_c1[(size_t)BATCH * CODE];
__device__ bf16   g_w3_0[(size_t)INTER * CODE], g_w3_1[(size_t)INTER * CODE];
__device__ bf16   g_d0[(size_t)BATCH * INTER],  g_d1[(size_t)BATCH * INTER];
__device__ bf16   g_w4_0[(size_t)N4P * INTER],  g_w4_1[(size_t)N4P * INTER];
__device__ int    g_flag_cnt;
__device__ int    g_flag_rows[BATCH];

// ===========================================================================
// R1 fp32 SGEMM (verbatim) — L1 only
// ===========================================================================
__global__ __launch_bounds__(256) void sgemm_bias_relu(
    const float* __restrict__ A, const float* __restrict__ B,
    const float* __restrict__ bias, float* __restrict__ C,
    int M, int N, int K)
{
    const int BM = 128, BN = 128, BK = 16;
    __shared__ float As[BK][BM + 4];
    __shared__ float Bs[BK][BN + 4];

    const int tid = threadIdx.x;
    const int tx = tid & 15;
    const int ty = tid >> 4;
    const int bm = blockIdx.y * BM;
    const int bn = blockIdx.x * BN;

    const float* Aptr = A + (size_t)bm * K;
    const float* Bptr = B + (size_t)bn * K;

    float acc[8][8];
#pragma unroll
    for (int i = 0; i < 8; i++)
#pragma unroll
        for (int j = 0; j < 8; j++) acc[i][j] = 0.0f;

    for (int k0 = 0; k0 < K; k0 += BK) {
#pragma unroll
        for (int i = 0; i < 2; i++) {
            int f = tid * 2 + i;
            int row = f >> 2;
            int k4 = (f & 3) * 4;
            float4 v = *(const float4*)(Aptr + (size_t)row * K + k0 + k4);
            As[k4 + 0][row] = v.x;
            As[k4 + 1][row] = v.y;
            As[k4 + 2][row] = v.z;
            As[k4 + 3][row] = v.w;
        }
#pragma unroll
        for (int i = 0; i < 2; i++) {
            int f = tid * 2 + i;
            int row = f >> 2;
            int k4 = (f & 3) * 4;
            float4 v = make_float4(0.f, 0.f, 0.f, 0.f);
            if (bn + row < N)
                v = *(const float4*)(Bptr + (size_t)row * K + k0 + k4);
            Bs[k4 + 0][row] = v.x;
            Bs[k4 + 1][row] = v.y;
            Bs[k4 + 2][row] = v.z;
            Bs[k4 + 3][row] = v.w;
        }
        __syncthreads();

#pragma unroll
        for (int k = 0; k < BK; k++) {
            float a[8], b[8];
            *(float4*)&a[0] = *(const float4*)&As[k][ty * 4];
            *(float4*)&a[4] = *(const float4*)&As[k][64 + ty * 4];
            *(float4*)&b[0] = *(const float4*)&Bs[k][tx * 4];
            *(float4*)&b[4] = *(const float4*)&Bs[k][64 + tx * 4];
#pragma unroll
            for (int i = 0; i < 8; i++)
#pragma unroll
                for (int j = 0; j < 8; j++)
                    acc[i][j] = fmaf(a[i], b[j], acc[i][j]);
        }
        __syncthreads();
    }

#pragma unroll
    for (int im = 0; im < 8; im++) {
        int m = bm + (im < 4 ? ty * 4 + im : 64 + ty * 4 + (im - 4));
        float* crow = C + (size_t)m * N;
#pragma unroll
        for (int jh = 0; jh < 2; jh++) {
            int n = bn + (jh == 0 ? tx * 4 : 64 + tx * 4);
            if (n < N) {
                float4 bv = *(const float4*)&bias[n];
                float4 r;
                r.x = fmaxf(acc[im][jh * 4 + 0] + bv.x, 0.0f);
                r.y = fmaxf(acc[im][jh * 4 + 1] + bv.y, 0.0f);
                r.z = fmaxf(acc[im][jh * 4 + 2] + bv.z, 0.0f);
                r.w = fmaxf(acc[im][jh * 4 + 3] + bv.w, 0.0f);
                *(float4*)&crow[n] = r;
            }
        }
    }
}

// ===========================================================================
// shared PTX helpers
// ===========================================================================
__device__ __forceinline__ uint32_t smem_u32(const void* p) {
    uint32_t a;
    asm("{ .reg .u64 t; cvta.to.shared.u64 t, %1; cvt.u32.u64 %0, t; }" : "=r"(a) : "l"(p));
    return a;
}
#define CP_ASYNC16(dst, src) \
    asm volatile("cp.async.cg.shared.global [%0], [%1], 16;" :: "r"(dst), "l"(src) : "memory")
#define CP_COMMIT()  asm volatile("cp.async.commit_group;" ::: "memory")
#define CP_WAIT(n)   asm volatile("cp.async.wait_group %0;" :: "n"(n) : "memory")

__device__ __forceinline__ void ldsm_x4(uint32_t& r0, uint32_t& r1, uint32_t& r2,
                                        uint32_t& r3, uint32_t addr) {
    asm volatile("ldmatrix.sync.aligned.m8n8.x4.shared.b16 {%0,%1,%2,%3}, [%4];"
        : "=r"(r0), "=r"(r1), "=r"(r2), "=r"(r3) : "r"(addr));
}
__device__ __forceinline__ void mma_bf(float* c, const uint32_t* a, const uint32_t* b) {
    asm volatile("mma.sync.aligned.m16n8k16.row.col.f32.bf16.bf16.f32 "
        "{%0,%1,%2,%3}, {%4,%5,%6,%7}, {%8,%9}, {%0,%1,%2,%3};"
        : "+f"(c[0]), "+f"(c[1]), "+f"(c[2]), "+f"(c[3])
        : "r"(a[0]), "r"(a[1]), "r"(a[2]), "r"(a[3]), "r"(b[0]), "r"(b[1]));
}
__device__ __forceinline__ void mma_fp16(float* c, const uint32_t* a, const uint32_t* b) {
    asm volatile("mma.sync.aligned.m16n8k16.row.col.f32.f16.f16.f32 "
        "{%0,%1,%2,%3}, {%4,%5,%6,%7}, {%8,%9}, {%0,%1,%2,%3};"
        : "+f"(c[0]), "+f"(c[1]), "+f"(c[2]), "+f"(c[3])
        : "r"(a[0]), "r"(a[1]), "r"(a[2]), "r"(a[3]), "r"(b[0]), "r"(b[1]));
}

#define ROWB   80
#define TILE_B (128 * ROWB)
#define SM_TILES 1024
#define SMEM_HMMA (SM_TILES + 2 * 4 * TILE_B)

// ===========================================================================
// L2 GEMM: fp16 scaled split, dual accumulators. c = relu(b2 + h @ W2^T), fp32.
// A parts: hh16, hl16(=lo*2048). B parts: w2h16, w2l16. K=1024, N=2048.
// ===========================================================================
__global__ __launch_bounds__(256, 1) void gemm_f16c(
    const __half* __restrict__ A0, const __half* __restrict__ A1,
    const __half* __restrict__ B0, const __half* __restrict__ B1,
    const float* __restrict__ bias, float* __restrict__ Cf)
{
    extern __shared__ char smem[];
    const uint32_t sbase = smem_u32(smem) + SM_TILES;
    const int tid  = threadIdx.x;
    const int warp = tid >> 5, lane = tid & 31;
    const int wm = (warp >> 2) * 64;
    const int wn = (warp & 3) * 32;
    const int m0 = blockIdx.y * 128;
    const int n0 = blockIdx.x * 128;
    const int Kp = INTER;

    if (tid < 128) ((float*)smem)[tid] = bias[n0 + tid];

    float acc1[4][4][4], acc2[4][4][4];
#pragma unroll
    for (int i = 0; i < 4; i++)
#pragma unroll
        for (int j = 0; j < 4; j++)
#pragma unroll
            for (int q = 0; q < 4; q++) { acc1[i][j][q] = 0.0f; acc2[i][j][q] = 0.0f; }

    const __half* Ap[2] = { A0, A1 };
    const __half* Bp[2] = { B0, B1 };
    const int nk = Kp / 32;

    auto load_stage = [&](int kc, int s) {
        const int k0 = kc * 32;
        const uint32_t stb = sbase + s * 4 * TILE_B;
#pragma unroll
        for (int t = 0; t < 4; t++) {
            const __half* base = (t < 2) ? (Ap[t] + (size_t)m0 * Kp)
                                         : (Bp[t - 2] + (size_t)n0 * Kp);
#pragma unroll
            for (int i = 0; i < 2; i++) {
                int f = tid + i * 256;
                int row = f >> 2, c = f & 3;
                uint32_t dst = stb + t * TILE_B + row * ROWB + c * 16;
                CP_ASYNC16(dst, base + (size_t)row * Kp + k0 + c * 8);
            }
        }
        CP_COMMIT();
    };

    auto compute_stage = [&](int s) {
        const uint32_t stb = sbase + s * 4 * TILE_B;
#pragma unroll
        for (int ks = 0; ks < 2; ks++) {
            uint32_t afr[2][4][4];
#pragma unroll
            for (int p = 0; p < 2; p++) {
                const uint32_t Ab = stb + p * TILE_B;
#pragma unroll
                for (int mf = 0; mf < 4; mf++) {
                    int row = wm + mf * 16 + (lane & 15);
                    uint32_t off = row * ROWB + ks * 32 + (lane >> 4) * 16;
                    ldsm_x4(afr[p][mf][0], afr[p][mf][1], afr[p][mf][2], afr[p][mf][3], Ab + off);
                }
            }
#pragma unroll
            for (int j = 0; j < 2; j++) {
                const uint32_t Bb = stb + (2 + j) * TILE_B;
                uint32_t bfr[4][2];
#pragma unroll
                for (int p = 0; p < 2; p++) {
                    int g = lane >> 3, ri = lane & 7;
                    int row = wn + p * 16 + ((g >> 1) << 3) + ri;
                    uint32_t off = row * ROWB + (2 * ks + (g & 1)) * 16;
                    uint32_t t0, t1, t2, t3;
                    ldsm_x4(t0, t1, t2, t3, Bb + off);
                    bfr[p*2][0] = t0; bfr[p*2][1] = t1;
                    bfr[p*2+1][0] = t2; bfr[p*2+1][1] = t3;
                }
                if (j == 0) {
#pragma unroll
                    for (int mf = 0; mf < 4; mf++)
#pragma unroll
                        for (int nf = 0; nf < 4; nf++) {
                            mma_fp16(acc1[mf][nf], afr[0][mf], bfr[nf]);   // Ah*Bh
                            mma_fp16(acc2[mf][nf], afr[1][mf], bfr[nf]);   // Al*Bh
                        }
                } else {
#pragma unroll
                    for (int mf = 0; mf < 4; mf++)
#pragma unroll
                        for (int nf = 0; nf < 4; nf++)
                            mma_fp16(acc2[mf][nf], afr[0][mf], bfr[nf]);   // Ah*Bl
                }
            }
        }
    };

    load_stage(0, 0);
    for (int kc = 0; kc < nk; kc++) {
        if (kc + 1 < nk) { load_stage(kc + 1, (kc + 1) & 1); CP_WAIT(1); }
        else             { CP_WAIT(0); }
        __syncthreads();
        compute_stage(kc & 1);
        __syncthreads();
    }

    const float* bs = (const float*)smem;
    const float INV = 1.0f / 2048.0f;
    const int lr = lane >> 2;
    const int lc = (lane & 3) * 2;
#pragma unroll
    for (int mf = 0; mf < 4; mf++) {
#pragma unroll
        for (int nf = 0; nf < 4; nf++) {
            int nrel = wn + nf * 8 + lc;
            int n = n0 + nrel;
            float b0 = bs[nrel], b1 = bs[nrel + 1];
#pragma unroll
            for (int half = 0; half < 2; half++) {
                int m = m0 + wm + mf * 16 + lr + half * 8;
                float v0 = fmaxf(fmaf(acc2[mf][nf][half*2+0], INV, acc1[mf][nf][half*2+0]) + b0, 0.0f);
                float v1 = fmaxf(fmaf(acc2[mf][nf][half*2+1], INV, acc1[mf][nf][half*2+1]) + b1, 0.0f);
                *(float2*)(Cf + (size_t)m * CODE + n) = make_float2(v0, v1);
            }
        }
    }
}

// ===========================================================================
// L3/L4 GEMM (bf16 2-part split, validated R7)
// ===========================================================================
template<int MODE>
__global__ __launch_bounds__(256, 1) void gemm_split2(
    const bf16* __restrict__ A0, const bf16* __restrict__ A1,
    const bf16* __restrict__ B0, const bf16* __restrict__ B1,
    const float* __restrict__ bias,
    float* __restrict__ Cf, bf16* __restrict__ C0, bf16* __restrict__ C1,
    int Kp, int Nvalid, int outStride)
{
    extern __shared__ char smem[];
    const uint32_t sbase = smem_u32(smem) + SM_TILES;
    const int tid  = threadIdx.x;
    const int warp = tid >> 5, lane = tid & 31;
    const int wm = (warp >> 2) * 64;
    const int wn = (warp & 3) * 32;
    const int m0 = blockIdx.y * 128;
    const int n0 = blockIdx.x * 128;

    if (tid < 128) {
        int n = n0 + tid;
        ((float*)smem)[tid] = (n < Nvalid) ? bias[n] : 0.0f;
    }

    float acc[4][4][4];
#pragma unroll
    for (int i = 0; i < 4; i++)
#pragma unroll
        for (int j = 0; j < 4; j++)
#pragma unroll
            for (int q = 0; q < 4; q++) acc[i][j][q] = 0.0f;

    const bf16* Ap[2] = { A0, A1 };
    const bf16* Bp[2] = { B0, B1 };
    const int nk = Kp / 32;

    auto load_stage = [&](int kc, int s) {
        const int k0 = kc * 32;
        const uint32_t stb = sbase + s * 4 * TILE_B;
#pragma unroll
        for (int t = 0; t < 4; t++) {
            const bf16* base = (t < 2) ? (Ap[t] + (size_t)m0 * Kp)
                                       : (Bp[t - 2] + (size_t)n0 * Kp);
#pragma unroll
            for (int i = 0; i < 2; i++) {
                int f = tid + i * 256;
                int row = f >> 2, c = f & 3;
                uint32_t dst = stb + t * TILE_B + row * ROWB + c * 16;
                CP_ASYNC16(dst, base + (size_t)row * Kp + k0 + c * 8);
            }
        }
        CP_COMMIT();
    };

    auto compute_stage = [&](int s) {
        const uint32_t stb = sbase + s * 4 * TILE_B;
#pragma unroll
        for (int ks = 0; ks < 2; ks++) {
            uint32_t afr[2][4][4];
#pragma unroll
            for (int p = 0; p < 2; p++) {
                const uint32_t Ab = stb + p * TILE_B;
#pragma unroll
                for (int mf = 0; mf < 4; mf++) {
                    int row = wm + mf * 16 + (lane & 15);
                    uint32_t off = row * ROWB + ks * 32 + (lane >> 4) * 16;
                    ldsm_x4(afr[p][mf][0], afr[p][mf][1], afr[p][mf][2], afr[p][mf][3], Ab + off);
                }
            }
#pragma unroll
            for (int j = 0; j < 2; j++) {
                const uint32_t Bb = stb + (2 + j) * TILE_B;
                uint32_t bfr[4][2];
#pragma unroll
                for (int p = 0; p < 2; p++) {
                    int g = lane >> 3, ri = lane & 7;
                    int row = wn + p * 16 + ((g >> 1) << 3) + ri;
                    uint32_t off = row * ROWB + (2 * ks + (g & 1)) * 16;
                    uint32_t t0, t1, t2, t3;
                    ldsm_x4(t0, t1, t2, t3, Bb + off);
                    bfr[p*2][0] = t0; bfr[p*2][1] = t1;
                    bfr[p*2+1][0] = t2; bfr[p*2+1][1] = t3;
                }
#pragma unroll
                for (int i = 0; i < 2 - j; i++)
#pragma unroll
                    for (int mf = 0; mf < 4; mf++)
#pragma unroll
                        for (int nf = 0; nf < 4; nf++)
                            mma_bf(acc[mf][nf], afr[i][mf], bfr[nf]);
            }
        }
    };

    load_stage(0, 0);
    for (int kc = 0; kc < nk; kc++) {
        if (kc + 1 < nk) { load_stage(kc + 1, (kc + 1) & 1); CP_WAIT(1); }
        else             { CP_WAIT(0); }
        __syncthreads();
        compute_stage(kc & 1);
        __syncthreads();
    }

    const float* bs = (const float*)smem;
    const int lr = lane >> 2;
    const int lc = (lane & 3) * 2;
#pragma unroll
    for (int mf = 0; mf < 4; mf++) {
#pragma unroll
        for (int nf = 0; nf < 4; nf++) {
            int nrel = wn + nf * 8 + lc;
            int n = n0 + nrel;
            float b0 = bs[nrel], b1 = bs[nrel + 1];
#pragma unroll
            for (int half = 0; half < 2; half++) {
                int m = m0 + wm + mf * 16 + lr + half * 8;
                float v0 = fmaxf(acc[mf][nf][half * 2 + 0] + b0, 0.0f);
                float v1 = fmaxf(acc[mf][nf][half * 2 + 1] + b1, 0.0f);
                if (MODE == 0) {
                    if (n < Nvalid)
                        *(float2*)(Cf + (size_t)m * outStride + n) = make_float2(v0, v1);
                } else {
                    __nv_bfloat162 p0, p1;
                    p0.x = __float2bfloat16(v0);
                    p0.y = __float2bfloat16(v1);
                    p1.x = __float2bfloat16(v0 - __bfloat162float(p0.x));
                    p1.y = __float2bfloat16(v1 - __bfloat162float(p0.y));
                    *(__nv_bfloat162*)(C0 + (size_t)m * outStride + n) = p0;
                    *(__nv_bfloat162*)(C1 + (size_t)m * outStride + n) = p1;
                }
            }
        }
    }
}

// ---------------------------------------------------------------------------
// split kernels
// ---------------------------------------------------------------------------
__global__ __launch_bounds__(256) void split16(
    const float* __restrict__ src, __half* __restrict__ H, __half* __restrict__ L, size_t n)
{
    size_t i = (size_t)blockIdx.x * blockDim.x + threadIdx.x;
    if (i >= n) return;
    float v = src[i];
    __half h = __float2half_rn(v);
    H[i] = h;
    L[i] = __float2half_rn((v - __half2float(h)) * 2048.0f);
}

__global__ __launch_bounds__(256) void split_pad2(
    const float* __restrict__ src, bf16* __restrict__ P0, bf16* __restrict__ P1,
    int srows, int scols, int orows, int ocols)
{
    size_t i = (size_t)blockIdx.x * blockDim.x + threadIdx.x;
    size_t tot = (size_t)orows * ocols;
    if (i >= tot) return;
    int r = (int)(i / ocols), c = (int)(i % ocols);
    float v = (r < srows && c < scols) ? src[(size_t)r * scols + c] : 0.0f;
    bf16 a = __float2bfloat16(v);
    P0[i] = a;
    P1[i] = __float2bfloat16(v - __bfloat162float(a));
}

// ---------------------------------------------------------------------------
// topk body (shared by flag-mode and fixup-mode kernels)
// ---------------------------------------------------------------------------
struct TopkSmem {
    unsigned int hist[256];
    unsigned int eqscan[256];
    float psum[256];
    float bmaxs[256];
    float ssum[NSTRIPE];
    float smask[NSTRIPE];
    unsigned int s_prefix, s_remk, s_total;
};

__device__ __forceinline__ void topk_body(
    TopkSmem& S, const float* __restrict__ C,
    bf16* __restrict__ C0, bf16* __restrict__ C1, int row, bool flagmode)
{
    const int tid = threadIdx.x;
    const float* crow = C + (size_t)row * CODE;

    float f[8];
    *(float4*)&f[0] = *(const float4*)(crow + tid * 8);
    *(float4*)&f[4] = *(const float4*)(crow + tid * 8 + 4);
    unsigned int u[8];
#pragma unroll
    for (int j = 0; j < 8; j++) u[j] = __float_as_uint(f[j]);

    if (tid == 0) { S.s_prefix = 0; S.s_remk = KNEUR; }
    __syncthreads();

#pragma unroll
    for (int pass = 0; pass < 4; pass++) {
        const int shift = 24 - pass * 8;
        const unsigned int pm = (pass == 0) ? 0u : (0xFFFFFFFFu << (shift + 8));
        S.hist[tid] = 0;
        __syncthreads();
        unsigned int pref = S.s_prefix;
#pragma unroll
        for (int j = 0; j < 8; j++)
            if ((u[j] & pm) == pref) atomicAdd(&S.hist[(u[j] >> shift) & 0xFF], 1u);
        __syncthreads();
        if (tid == 0) {
            unsigned int remk = S.s_remk, acc = 0;
            int b = 255;
            for (; b > 0; b--) { acc += S.hist[b]; if (acc >= remk) break; }
            if (acc < remk) acc += S.hist[0];
            S.s_prefix = pref | ((unsigned int)b << shift);
            S.s_remk = remk - (acc - S.hist[b]);
        }
        __syncthreads();
    }

    const unsigned int t = S.s_prefix;
    const unsigned int need_eq = S.s_remk;

    unsigned int cnt = 0;
    float bmax = 0.0f;
#pragma unroll
    for (int j = 0; j < 8; j++) {
        cnt += (u[j] == t);
        if (u[j] < t) bmax = fmaxf(bmax, f[j]);
    }
    S.eqscan[tid] = cnt;
    S.bmaxs[tid] = bmax;
    __syncthreads();
    if (tid == 0) {
        unsigned int run = 0;
        for (int i = 0; i < 256; i++) { unsigned int v = S.eqscan[i]; S.eqscan[i] = run; run += v; }
        S.s_total = run;
    }
#pragma unroll
    for (int off = 128; off > 0; off >>= 1) {
        __syncthreads();
        if (tid < off) S.bmaxs[tid] = fmaxf(S.bmaxs[tid], S.bmaxs[tid + off]);
    }
    __syncthreads();

    unsigned int rank = S.eqscan[tid];
    float part = 0.0f;
#pragma unroll
    for (int j = 0; j < 8; j++) {
        bool keep;
        if (u[j] > t) keep = true;
        else if (u[j] == t) { keep = (rank < need_eq); rank++; }
        else keep = false;
        if (!keep) f[j] = 0.0f;
        part += f[j];
    }
    S.psum[tid] = part;
    __syncthreads();

    if (tid < NSTRIPE) {
        float s = 0.0f;
#pragma unroll
        for (int i = 0; i < 8; i++) s += S.psum[tid * 8 + i];
        S.ssum[tid] = s;
    }
    __syncthreads();

    if (tid == 0) {
        bool sel[NSTRIPE];
#pragma unroll
        for (int s = 0; s < NSTRIPE; s++) sel[s] = false;
        float v4 = 0.0f, v5 = 0.0f;
        for (int it = 0; it < KSTRIPE + 1; it++) {
            int best = -1; float bv = -1.0f;
            for (int s = 0; s < NSTRIPE; s++)
                if (!sel[s] && S.ssum[s] > bv) { bv = S.ssum[s]; best = s; }
            if (it < KSTRIPE) { sel[best] = true; if (it == KSTRIPE - 1) v4 = bv; }
            else v5 = bv;
        }
#pragma unroll
        for (int s = 0; s < NSTRIPE; s++) S.smask[s] = sel[s] ? 1.0f : 0.0f;

        if (flagmode) {
            float gap_n = __uint_as_float(t) - S.bmaxs[0];
            if (need_eq < S.s_total) gap_n = 0.0f;   // tie straddles boundary
            float gap_s = v4 - v5;
            if (gap_n < TAU1 || gap_s < TAU2) {
                int ix = atomicAdd(&g_flag_cnt, 1);
                g_flag_rows[ix] = row;
            }
        }
    }
    __syncthreads();

    const float sm = S.smask[tid >> 3];
    bf16* hrow = C0 + (size_t)row * CODE + tid * 8;
    bf16* lrow = C1 + (size_t)row * CODE + tid * 8;
#pragma unroll
    for (int j = 0; j < 8; j += 2) {
        float v0 = f[j] * sm, v1 = f[j+1] * sm;
        __nv_bfloat162 h2, l2;
        h2.x = __float2bfloat16(v0);
        h2.y = __float2bfloat16(v1);
        l2.x = __float2bfloat16(v0 - __bfloat162float(h2.x));
        l2.y = __float2bfloat16(v1 - __bfloat162float(h2.y));
        *(__nv_bfloat162*)&hrow[j] = h2;
        *(__nv_bfloat162*)&lrow[j] = l2;
    }
}

__global__ __launch_bounds__(256) void topk_flag_kernel(
    const float* __restrict__ C, bf16* __restrict__ C0, bf16* __restrict__ C1)
{
    __shared__ TopkSmem S;
    topk_body(S, C, C0, C1, blockIdx.x, true);
}

__global__ __launch_bounds__(256) void reset_cnt_kernel()
{
    if (threadIdx.x == 0 && blockIdx.x == 0) g_flag_cnt = 0;
}

// Phase A: exact recompute of flagged c rows (serial fmaf chain == R1 bits)
__global__ __launch_bounds__(256) void fixup_exact_kernel(
    const float* __restrict__ h, const float* __restrict__ W2,
    const float* __restrict__ b2, float* __restrict__ c)
{
    __shared__ float hs[8][INTER];
    const int tid = threadIdx.x;
    const int nf = g_flag_cnt;

    for (int base = blockIdx.x * 8; base < nf; base += gridDim.x * 8) {
        int nrows = nf - base; if (nrows > 8) nrows = 8;
        for (int r = 0; r < nrows; r++) {
            int row = g_flag_rows[base + r];
            for (int k = tid; k < INTER; k += 256)
                hs[r][k] = h[(size_t)row * INTER + k];
        }
        __syncthreads();
#pragma unroll 1
        for (int jj = 0; jj < 8; jj++) {
            int j = tid + jj * 256;
            const float* w = W2 + (size_t)j * INTER;
            float acc[8];
#pragma unroll
            for (int r = 0; r < 8; r++) acc[r] = 0.0f;
            for (int k = 0; k < INTER; k += 4) {
                float4 w4 = *(const float4*)(w + k);
#pragma unroll
                for (int r = 0; r < 8; r++) {
                    acc[r] = fmaf(hs[r][k + 0], w4.x, acc[r]);
                    acc[r] = fmaf(hs[r][k + 1], w4.y, acc[r]);
                    acc[r] = fmaf(hs[r][k + 2], w4.z, acc[r]);
                    acc[r] = fmaf(hs[r][k + 3], w4.w, acc[r]);
                }
            }
            float bj = b2[j];
            for (int r = 0; r < nrows; r++) {
                int row = g_flag_rows[base + r];
                c[(size_t)row * CODE + j] = fmaxf(acc[r] + bj, 0.0f);
            }
        }
        __syncthreads();
    }
}

// Phase B: exact re-selection for flagged rows
__global__ __launch_bounds__(256) void fixup_topk_kernel(
    const float* __restrict__ C, bf16* __restrict__ C0, bf16* __restrict__ C1)
{
    __shared__ TopkSmem S;
    const int nf = g_flag_cnt;
    for (int i = blockIdx.x; i < nf; i += gridDim.x) {
        topk_body(S, C, C0, C1, g_flag_rows[i], false);
        __syncthreads();
    }
}

// ---------------------------------------------------------------------------
extern "C" void kernel_launch(void* const* d_in, const int* in_sizes, int n_in,
                              void* d_out, int out_size)
{
    const float* x  = (const float*)d_in[0];
    const float* W1 = (const float*)d_in[1];
    const float* b1 = (const float*)d_in[2];
    const float* W2 = (const float*)d_in[3];
    const float* b2 = (const float*)d_in[4];
    const float* W3 = (const float*)d_in[5];
    const float* b3 = (const float*)d_in[6];
    const float* W4 = (const float*)d_in[7];
    const float* b4 = (const float*)d_in[8];
    float* out = (float*)d_out;

    float *h, *c;
    __half *hh16, *hl16, *w2h16, *w2l16;
    bf16 *c0, *c1, *w30, *w31, *d0, *d1, *w40, *w41;
    cudaGetSymbolAddress((void**)&h, g_h);
    cudaGetSymbolAddress((void**)&c, g_c);
    cudaGetSymbolAddress((void**)&hh16, g_hh16);  cudaGetSymbolAddress((void**)&hl16, g_hl16);
    cudaGetSymbolAddress((void**)&w2h16, g_w2h16); cudaGetSymbolAddress((void**)&w2l16, g_w2l16);
    cudaGetSymbolAddress((void**)&c0, g_c0);   cudaGetSymbolAddress((void**)&c1, g_c1);
    cudaGetSymbolAddress((void**)&w30, g_w3_0); cudaGetSymbolAddress((void**)&w31, g_w3_1);
    cudaGetSymbolAddress((void**)&d0, g_d0);   cudaGetSymbolAddress((void**)&d1, g_d1);
    cudaGetSymbolAddress((void**)&w40, g_w4_0); cudaGetSymbolAddress((void**)&w41, g_w4_1);

    cudaFuncSetAttribute(gemm_f16c, cudaFuncAttributeMaxDynamicSharedMemorySize, SMEM_HMMA);
    cudaFuncSetAttribute(gemm_split2<0>, cudaFuncAttributeMaxDynamicSharedMemorySize, SMEM_HMMA);
    cudaFuncSetAttribute(gemm_split2<1>, cudaFuncAttributeMaxDynamicSharedMemorySize, SMEM_HMMA);

    auto gs = [](size_t n) { return (unsigned)((n + 255) / 256); };

    // weight prep
    split16<<<gs((size_t)CODE * INTER), 256>>>(W2, w2h16, w2l16, (size_t)CODE * INTER);
    split_pad2<<<gs((size_t)INTER * CODE), 256>>>(W3, w30, w31, INTER, CODE, INTER, CODE);
    split_pad2<<<gs((size_t)N4P * INTER), 256>>>(W4, w40, w41, IN_DIM, INTER, N4P, INTER);

    // L1 (bit-anchor fp32)
    sgemm_bias_relu<<<dim3(INTER / 128, BATCH / 128), 256>>>(x, W1, b1, h, BATCH, INTER, IN_DIM);

    // h split + L2 fp16-split HMMA
    split16<<<gs((size_t)BATCH * INTER), 256>>>(h, hh16, hl16, (size_t)BATCH * INTER);
    gemm_f16c<<<dim3(CODE / 128, BATCH / 128), 256, SMEM_HMMA>>>(
        hh16, hl16, w2h16, w2l16, b2, c);

    // topk with boundary margins; exact fixup for flagged rows
    reset_cnt_kernel<<<1, 32>>>();
    topk_flag_kernel<<<BATCH, 256>>>(c, c0, c1);
    fixup_exact_kernel<<<256, 256>>>(h, W2, b2, c);
    fixup_topk_kernel<<<512, 256>>>(c, c0, c1);

    // L3, L4 (validated HMMA split)
    gemm_split2<1><<<dim3(INTER / 128, BATCH / 128), 256, SMEM_HMMA>>>(
        c0, c1, w30, w31, b3, nullptr, d0, d1, CODE, INTER, INTER);
    gemm_split2<0><<<dim3(N4P / 128, BATCH / 128), 256, SMEM_HMMA>>>(
        d0, d1, w40, w41, b4, out, nullptr, nullptr, INTER, IN_DIM, IN_DIM);
}

// round 9
// speedup vs baseline: 1.6352x; 1.2308x over previous
#include <cuda_runtime.h>
#include <cuda_bf16.h>
#include <cuda_fp16.h>
#include <cstdint>

// ---------------------------------------------------------------------------
// Net_46368466928157 — round 9:
//   L1: R1 fp32 SGEMM (bit-anchor), epilogue fused h -> fp16 pair
//   L2: fp16 scaled 2-part split HMMA (validated R8)
//   topk: margins + exact fixup (validated R8); emits compact (idx,val) lists
//   L3: sparse row-gather GEMV in exact fp32 (<=64 nnz/row), writes d bf16 pair
//   L4: bf16 2-part split HMMA (validated R7)
// ---------------------------------------------------------------------------

#define BATCH   16384
#define IN_DIM  784
#define INTER   1024
#define CODE    2048
#define N4P     896
#define NSTRIPE 32
#define KNEUR   64
#define KSTRIPE 4

#define TAU1 2e-5f
#define TAU2 2e-3f

typedef __nv_bfloat16 bf16;

// ---- scratch --------------------------------------------------------------
__device__ float  g_h[(size_t)BATCH * INTER];
__device__ float  g_c[(size_t)BATCH * CODE];
__device__ __half g_hh16[(size_t)BATCH * INTER], g_hl16[(size_t)BATCH * INTER];
__device__ __half g_w2h16[(size_t)CODE * INTER], g_w2l16[(size_t)CODE * INTER];
__device__ float  g_w3t[(size_t)CODE * INTER];       // W3^T [2048,1024]
__device__ bf16   g_d0[(size_t)BATCH * INTER],  g_d1[(size_t)BATCH * INTER];
__device__ bf16   g_w4_0[(size_t)N4P * INTER],  g_w4_1[(size_t)N4P * INTER];
__device__ int    g_flag_cnt;
__device__ int    g_flag_rows[BATCH];
__device__ int    g_cnt[BATCH];
__device__ int    g_idx[(size_t)BATCH * KNEUR];
__device__ float  g_val[(size_t)BATCH * KNEUR];

// ===========================================================================
// L1: R1 fp32 SGEMM, identical FMA sequence; epilogue also emits fp16 pair.
// ===========================================================================
__global__ __launch_bounds__(256) void sgemm_bias_relu(
    const float* __restrict__ A, const float* __restrict__ B,
    const float* __restrict__ bias, float* __restrict__ C,
    __half* __restrict__ Hh, __half* __restrict__ Hl,
    int M, int N, int K)
{
    const int BM = 128, BN = 128, BK = 16;
    __shared__ float As[BK][BM + 4];
    __shared__ float Bs[BK][BN + 4];

    const int tid = threadIdx.x;
    const int tx = tid & 15;
    const int ty = tid >> 4;
    const int bm = blockIdx.y * BM;
    const int bn = blockIdx.x * BN;

    const float* Aptr = A + (size_t)bm * K;
    const float* Bptr = B + (size_t)bn * K;

    float acc[8][8];
#pragma unroll
    for (int i = 0; i < 8; i++)
#pragma unroll
        for (int j = 0; j < 8; j++) acc[i][j] = 0.0f;

    for (int k0 = 0; k0 < K; k0 += BK) {
#pragma unroll
        for (int i = 0; i < 2; i++) {
            int f = tid * 2 + i;
            int row = f >> 2;
            int k4 = (f & 3) * 4;
            float4 v = *(const float4*)(Aptr + (size_t)row * K + k0 + k4);
            As[k4 + 0][row] = v.x;
            As[k4 + 1][row] = v.y;
            As[k4 + 2][row] = v.z;
            As[k4 + 3][row] = v.w;
        }
#pragma unroll
        for (int i = 0; i < 2; i++) {
            int f = tid * 2 + i;
            int row = f >> 2;
            int k4 = (f & 3) * 4;
            float4 v = make_float4(0.f, 0.f, 0.f, 0.f);
            if (bn + row < N)
                v = *(const float4*)(Bptr + (size_t)row * K + k0 + k4);
            Bs[k4 + 0][row] = v.x;
            Bs[k4 + 1][row] = v.y;
            Bs[k4 + 2][row] = v.z;
            Bs[k4 + 3][row] = v.w;
        }
        __syncthreads();

#pragma unroll
        for (int k = 0; k < BK; k++) {
            float a[8], b[8];
            *(float4*)&a[0] = *(const float4*)&As[k][ty * 4];
            *(float4*)&a[4] = *(const float4*)&As[k][64 + ty * 4];
            *(float4*)&b[0] = *(const float4*)&Bs[k][tx * 4];
            *(float4*)&b[4] = *(const float4*)&Bs[k][64 + tx * 4];
#pragma unroll
            for (int i = 0; i < 8; i++)
#pragma unroll
                for (int j = 0; j < 8; j++)
                    acc[i][j] = fmaf(a[i], b[j], acc[i][j]);
        }
        __syncthreads();
    }

#pragma unroll
    for (int im = 0; im < 8; im++) {
        int m = bm + (im < 4 ? ty * 4 + im : 64 + ty * 4 + (im - 4));
        float* crow = C + (size_t)m * N;
#pragma unroll
        for (int jh = 0; jh < 2; jh++) {
            int n = bn + (jh == 0 ? tx * 4 : 64 + tx * 4);
            if (n < N) {
                float4 bv = *(const float4*)&bias[n];
                float4 r;
                r.x = fmaxf(acc[im][jh * 4 + 0] + bv.x, 0.0f);
                r.y = fmaxf(acc[im][jh * 4 + 1] + bv.y, 0.0f);
                r.z = fmaxf(acc[im][jh * 4 + 2] + bv.z, 0.0f);
                r.w = fmaxf(acc[im][jh * 4 + 3] + bv.w, 0.0f);
                *(float4*)&crow[n] = r;
                if (Hh) {
                    __half h0 = __float2half_rn(r.x), h1 = __float2half_rn(r.y);
                    __half h2 = __float2half_rn(r.z), h3 = __float2half_rn(r.w);
                    __half2 hh0, hh1, ll0, ll1;
                    hh0 = __halves2half2(h0, h1);
                    hh1 = __halves2half2(h2, h3);
                    ll0 = __halves2half2(__float2half_rn((r.x - __half2float(h0)) * 2048.0f),
                                         __float2half_rn((r.y - __half2float(h1)) * 2048.0f));
                    ll1 = __halves2half2(__float2half_rn((r.z - __half2float(h2)) * 2048.0f),
                                         __float2half_rn((r.w - __half2float(h3)) * 2048.0f));
                    *(__half2*)(Hh + (size_t)m * N + n)     = hh0;
                    *(__half2*)(Hh + (size_t)m * N + n + 2) = hh1;
                    *(__half2*)(Hl + (size_t)m * N + n)     = ll0;
                    *(__half2*)(Hl + (size_t)m * N + n + 2) = ll1;
                }
            }
        }
    }
}

// ===========================================================================
// shared PTX helpers
// ===========================================================================
__device__ __forceinline__ uint32_t smem_u32(const void* p) {
    uint32_t a;
    asm("{ .reg .u64 t; cvta.to.shared.u64 t, %1; cvt.u32.u64 %0, t; }" : "=r"(a) : "l"(p));
    return a;
}
#define CP_ASYNC16(dst, src) \
    asm volatile("cp.async.cg.shared.global [%0], [%1], 16;" :: "r"(dst), "l"(src) : "memory")
#define CP_COMMIT()  asm volatile("cp.async.commit_group;" ::: "memory")
#define CP_WAIT(n)   asm volatile("cp.async.wait_group %0;" :: "n"(n) : "memory")

__device__ __forceinline__ void ldsm_x4(uint32_t& r0, uint32_t& r1, uint32_t& r2,
                                        uint32_t& r3, uint32_t addr) {
    asm volatile("ldmatrix.sync.aligned.m8n8.x4.shared.b16 {%0,%1,%2,%3}, [%4];"
        : "=r"(r0), "=r"(r1), "=r"(r2), "=r"(r3) : "r"(addr));
}
__device__ __forceinline__ void mma_bf(float* c, const uint32_t* a, const uint32_t* b) {
    asm volatile("mma.sync.aligned.m16n8k16.row.col.f32.bf16.bf16.f32 "
        "{%0,%1,%2,%3}, {%4,%5,%6,%7}, {%8,%9}, {%0,%1,%2,%3};"
        : "+f"(c[0]), "+f"(c[1]), "+f"(c[2]), "+f"(c[3])
        : "r"(a[0]), "r"(a[1]), "r"(a[2]), "r"(a[3]), "r"(b[0]), "r"(b[1]));
}
__device__ __forceinline__ void mma_fp16(float* c, const uint32_t* a, const uint32_t* b) {
    asm volatile("mma.sync.aligned.m16n8k16.row.col.f32.f16.f16.f32 "
        "{%0,%1,%2,%3}, {%4,%5,%6,%7}, {%8,%9}, {%0,%1,%2,%3};"
        : "+f"(c[0]), "+f"(c[1]), "+f"(c[2]), "+f"(c[3])
        : "r"(a[0]), "r"(a[1]), "r"(a[2]), "r"(a[3]), "r"(b[0]), "r"(b[1]));
}

#define ROWB   80
#define TILE_B (128 * ROWB)
#define SM_TILES 1024
#define SMEM_HMMA (SM_TILES + 2 * 4 * TILE_B)

// ===========================================================================
// L2: fp16 scaled split HMMA (validated R8)
// ===========================================================================
__global__ __launch_bounds__(256, 1) void gemm_f16c(
    const __half* __restrict__ A0, const __half* __restrict__ A1,
    const __half* __restrict__ B0, const __half* __restrict__ B1,
    const float* __restrict__ bias, float* __restrict__ Cf)
{
    extern __shared__ char smem[];
    const uint32_t sbase = smem_u32(smem) + SM_TILES;
    const int tid  = threadIdx.x;
    const int warp = tid >> 5, lane = tid & 31;
    const int wm = (warp >> 2) * 64;
    const int wn = (warp & 3) * 32;
    const int m0 = blockIdx.y * 128;
    const int n0 = blockIdx.x * 128;
    const int Kp = INTER;

    if (tid < 128) ((float*)smem)[tid] = bias[n0 + tid];

    float acc1[4][4][4], acc2[4][4][4];
#pragma unroll
    for (int i = 0; i < 4; i++)
#pragma unroll
        for (int j = 0; j < 4; j++)
#pragma unroll
            for (int q = 0; q < 4; q++) { acc1[i][j][q] = 0.0f; acc2[i][j][q] = 0.0f; }

    const __half* Ap[2] = { A0, A1 };
    const __half* Bp[2] = { B0, B1 };
    const int nk = Kp / 32;

    auto load_stage = [&](int kc, int s) {
        const int k0 = kc * 32;
        const uint32_t stb = sbase + s * 4 * TILE_B;
#pragma unroll
        for (int t = 0; t < 4; t++) {
            const __half* base = (t < 2) ? (Ap[t] + (size_t)m0 * Kp)
                                         : (Bp[t - 2] + (size_t)n0 * Kp);
#pragma unroll
            for (int i = 0; i < 2; i++) {
                int f = tid + i * 256;
                int row = f >> 2, c = f & 3;
                uint32_t dst = stb + t * TILE_B + row * ROWB + c * 16;
                CP_ASYNC16(dst, base + (size_t)row * Kp + k0 + c * 8);
            }
        }
        CP_COMMIT();
    };

    auto compute_stage = [&](int s) {
        const uint32_t stb = sbase + s * 4 * TILE_B;
#pragma unroll
        for (int ks = 0; ks < 2; ks++) {
            uint32_t afr[2][4][4];
#pragma unroll
            for (int p = 0; p < 2; p++) {
                const uint32_t Ab = stb + p * TILE_B;
#pragma unroll
                for (int mf = 0; mf < 4; mf++) {
                    int row = wm + mf * 16 + (lane & 15);
                    uint32_t off = row * ROWB + ks * 32 + (lane >> 4) * 16;
                    ldsm_x4(afr[p][mf][0], afr[p][mf][1], afr[p][mf][2], afr[p][mf][3], Ab + off);
                }
            }
#pragma unroll
            for (int j = 0; j < 2; j++) {
                const uint32_t Bb = stb + (2 + j) * TILE_B;
                uint32_t bfr[4][2];
#pragma unroll
                for (int p = 0; p < 2; p++) {
                    int g = lane >> 3, ri = lane & 7;
                    int row = wn + p * 16 + ((g >> 1) << 3) + ri;
                    uint32_t off = row * ROWB + (2 * ks + (g & 1)) * 16;
                    uint32_t t0, t1, t2, t3;
                    ldsm_x4(t0, t1, t2, t3, Bb + off);
                    bfr[p*2][0] = t0; bfr[p*2][1] = t1;
                    bfr[p*2+1][0] = t2; bfr[p*2+1][1] = t3;
                }
                if (j == 0) {
#pragma unroll
                    for (int mf = 0; mf < 4; mf++)
#pragma unroll
                        for (int nf = 0; nf < 4; nf++) {
                            mma_fp16(acc1[mf][nf], afr[0][mf], bfr[nf]);
                            mma_fp16(acc2[mf][nf], afr[1][mf], bfr[nf]);
                        }
                } else {
#pragma unroll
                    for (int mf = 0; mf < 4; mf++)
#pragma unroll
                        for (int nf = 0; nf < 4; nf++)
                            mma_fp16(acc2[mf][nf], afr[0][mf], bfr[nf]);
                }
            }
        }
    };

    load_stage(0, 0);
    for (int kc = 0; kc < nk; kc++) {
        if (kc + 1 < nk) { load_stage(kc + 1, (kc + 1) & 1); CP_WAIT(1); }
        else             { CP_WAIT(0); }
        __syncthreads();
        compute_stage(kc & 1);
        __syncthreads();
    }

    const float* bs = (const float*)smem;
    const float INV = 1.0f / 2048.0f;
    const int lr = lane >> 2;
    const int lc = (lane & 3) * 2;
#pragma unroll
    for (int mf = 0; mf < 4; mf++) {
#pragma unroll
        for (int nf = 0; nf < 4; nf++) {
            int nrel = wn + nf * 8 + lc;
            int n = n0 + nrel;
            float b0 = bs[nrel], b1 = bs[nrel + 1];
#pragma unroll
            for (int half = 0; half < 2; half++) {
                int m = m0 + wm + mf * 16 + lr + half * 8;
                float v0 = fmaxf(fmaf(acc2[mf][nf][half*2+0], INV, acc1[mf][nf][half*2+0]) + b0, 0.0f);
                float v1 = fmaxf(fmaf(acc2[mf][nf][half*2+1], INV, acc1[mf][nf][half*2+1]) + b1, 0.0f);
                *(float2*)(Cf + (size_t)m * CODE + n) = make_float2(v0, v1);
            }
        }
    }
}

// ===========================================================================
// L4 GEMM (bf16 2-part split, MODE0 fp32 out — validated R7)
// ===========================================================================
__global__ __launch_bounds__(256, 1) void gemm_split2_f(
    const bf16* __restrict__ A0, const bf16* __restrict__ A1,
    const bf16* __restrict__ B0, const bf16* __restrict__ B1,
    const float* __restrict__ bias, float* __restrict__ Cf,
    int Kp, int Nvalid, int outStride)
{
    extern __shared__ char smem[];
    const uint32_t sbase = smem_u32(smem) + SM_TILES;
    const int tid  = threadIdx.x;
    const int warp = tid >> 5, lane = tid & 31;
    const int wm = (warp >> 2) * 64;
    const int wn = (warp & 3) * 32;
    const int m0 = blockIdx.y * 128;
    const int n0 = blockIdx.x * 128;

    if (tid < 128) {
        int n = n0 + tid;
        ((float*)smem)[tid] = (n < Nvalid) ? bias[n] : 0.0f;
    }

    float acc[4][4][4];
#pragma unroll
    for (int i = 0; i < 4; i++)
#pragma unroll
        for (int j = 0; j < 4; j++)
#pragma unroll
            for (int q = 0; q < 4; q++) acc[i][j][q] = 0.0f;

    const bf16* Ap[2] = { A0, A1 };
    const bf16* Bp[2] = { B0, B1 };
    const int nk = Kp / 32;

    auto load_stage = [&](int kc, int s) {
        const int k0 = kc * 32;
        const uint32_t stb = sbase + s * 4 * TILE_B;
#pragma unroll
        for (int t = 0; t < 4; t++) {
            const bf16* base = (t < 2) ? (Ap[t] + (size_t)m0 * Kp)
                                       : (Bp[t - 2] + (size_t)n0 * Kp);
#pragma unroll
            for (int i = 0; i < 2; i++) {
                int f = tid + i * 256;
                int row = f >> 2, c = f & 3;
                uint32_t dst = stb + t * TILE_B + row * ROWB + c * 16;
                CP_ASYNC16(dst, base + (size_t)row * Kp + k0 + c * 8);
            }
        }
        CP_COMMIT();
    };

    auto compute_stage = [&](int s) {
        const uint32_t stb = sbase + s * 4 * TILE_B;
#pragma unroll
        for (int ks = 0; ks < 2; ks++) {
            uint32_t afr[2][4][4];
#pragma unroll
            for (int p = 0; p < 2; p++) {
                const uint32_t Ab = stb + p * TILE_B;
#pragma unroll
                for (int mf = 0; mf < 4; mf++) {
                    int row = wm + mf * 16 + (lane & 15);
                    uint32_t off = row * ROWB + ks * 32 + (lane >> 4) * 16;
                    ldsm_x4(afr[p][mf][0], afr[p][mf][1], afr[p][mf][2], afr[p][mf][3], Ab + off);
                }
            }
#pragma unroll
            for (int j = 0; j < 2; j++) {
                const uint32_t Bb = stb + (2 + j) * TILE_B;
                uint32_t bfr[4][2];
#pragma unroll
                for (int p = 0; p < 2; p++) {
                    int g = lane >> 3, ri = lane & 7;
                    int row = wn + p * 16 + ((g >> 1) << 3) + ri;
                    uint32_t off = row * ROWB + (2 * ks + (g & 1)) * 16;
                    uint32_t t0, t1, t2, t3;
                    ldsm_x4(t0, t1, t2, t3, Bb + off);
                    bfr[p*2][0] = t0; bfr[p*2][1] = t1;
                    bfr[p*2+1][0] = t2; bfr[p*2+1][1] = t3;
                }
#pragma unroll
                for (int i = 0; i < 2 - j; i++)
#pragma unroll
                    for (int mf = 0; mf < 4; mf++)
#pragma unroll
                        for (int nf = 0; nf < 4; nf++)
                            mma_bf(acc[mf][nf], afr[i][mf], bfr[nf]);
            }
        }
    };

    load_stage(0, 0);
    for (int kc = 0; kc < nk; kc++) {
        if (kc + 1 < nk) { load_stage(kc + 1, (kc + 1) & 1); CP_WAIT(1); }
        else             { CP_WAIT(0); }
        __syncthreads();
        compute_stage(kc & 1);
        __syncthreads();
    }

    const float* bs = (const float*)smem;
    const int lr = lane >> 2;
    const int lc = (lane & 3) * 2;
#pragma unroll
    for (int mf = 0; mf < 4; mf++) {
#pragma unroll
        for (int nf = 0; nf < 4; nf++) {
            int nrel = wn + nf * 8 + lc;
            int n = n0 + nrel;
            float b0 = bs[nrel], b1 = bs[nrel + 1];
#pragma unroll
            for (int half = 0; half < 2; half++) {
                int m = m0 + wm + mf * 16 + lr + half * 8;
                float v0 = fmaxf(acc[mf][nf][half * 2 + 0] + b0, 0.0f);
                float v1 = fmaxf(acc[mf][nf][half * 2 + 1] + b1, 0.0f);
                if (n < Nvalid)
                    *(float2*)(Cf + (size_t)m * outStride + n) = make_float2(v0, v1);
            }
        }
    }
}

// ---------------------------------------------------------------------------
// prep kernels
// ---------------------------------------------------------------------------
__global__ __launch_bounds__(256) void split16(
    const float* __restrict__ src, __half* __restrict__ H, __half* __restrict__ L, size_t n)
{
    size_t i = (size_t)blockIdx.x * blockDim.x + threadIdx.x;
    if (i >= n) return;
    float v = src[i];
    __half h = __float2half_rn(v);
    H[i] = h;
    L[i] = __float2half_rn((v - __half2float(h)) * 2048.0f);
}

__global__ __launch_bounds__(256) void split_pad2(
    const float* __restrict__ src, bf16* __restrict__ P0, bf16* __restrict__ P1,
    int srows, int scols, int orows, int ocols)
{
    size_t i = (size_t)blockIdx.x * blockDim.x + threadIdx.x;
    size_t tot = (size_t)orows * ocols;
    if (i >= tot) return;
    int r = (int)(i / ocols), c = (int)(i % ocols);
    float v = (r < srows && c < scols) ? src[(size_t)r * scols + c] : 0.0f;
    bf16 a = __float2bfloat16(v);
    P0[i] = a;
    P1[i] = __float2bfloat16(v - __bfloat162float(a));
}

// W3 [INTER,CODE] -> W3T [CODE,INTER]
__global__ void transpose_w3(const float* __restrict__ W3, float* __restrict__ W3T)
{
    __shared__ float t[32][33];
    int bx = blockIdx.x * 32;   // CODE index
    int by = blockIdx.y * 32;   // INTER index
    for (int i = threadIdx.y; i < 32; i += 8)
        t[i][threadIdx.x] = W3[(size_t)(by + i) * CODE + bx + threadIdx.x];
    __syncthreads();
    for (int i = threadIdx.y; i < 32; i += 8)
        W3T[(size_t)(bx + i) * INTER + by + threadIdx.x] = t[threadIdx.x][i];
}

// ---------------------------------------------------------------------------
// topk body — emits compact (idx, val) list per row (deterministic order)
// ---------------------------------------------------------------------------
struct TopkSmem {
    unsigned int hist[256];
    unsigned int eqscan[256];
    float psum[256];
    float bmaxs[256];
    float ssum[NSTRIPE];
    float smask[NSTRIPE];
    unsigned int s_prefix, s_remk, s_total;
};

__device__ __forceinline__ void topk_body(
    TopkSmem& S, const float* __restrict__ C, int row, bool flagmode)
{
    const int tid = threadIdx.x;
    const float* crow = C + (size_t)row * CODE;

    float f[8];
    *(float4*)&f[0] = *(const float4*)(crow + tid * 8);
    *(float4*)&f[4] = *(const float4*)(crow + tid * 8 + 4);
    unsigned int u[8];
#pragma unroll
    for (int j = 0; j < 8; j++) u[j] = __float_as_uint(f[j]);

    if (tid == 0) { S.s_prefix = 0; S.s_remk = KNEUR; }
    __syncthreads();

#pragma unroll
    for (int pass = 0; pass < 4; pass++) {
        const int shift = 24 - pass * 8;
        const unsigned int pm = (pass == 0) ? 0u : (0xFFFFFFFFu << (shift + 8));
        S.hist[tid] = 0;
        __syncthreads();
        unsigned int pref = S.s_prefix;
#pragma unroll
        for (int j = 0; j < 8; j++)
            if ((u[j] & pm) == pref) atomicAdd(&S.hist[(u[j] >> shift) & 0xFF], 1u);
        __syncthreads();
        if (tid == 0) {
            unsigned int remk = S.s_remk, acc = 0;
            int b = 255;
            for (; b > 0; b--) { acc += S.hist[b]; if (acc >= remk) break; }
            if (acc < remk) acc += S.hist[0];
            S.s_prefix = pref | ((unsigned int)b << shift);
            S.s_remk = remk - (acc - S.hist[b]);
        }
        __syncthreads();
    }

    const unsigned int t = S.s_prefix;
    const unsigned int need_eq = S.s_remk;

    unsigned int cnt = 0;
    float bmax = 0.0f;
#pragma unroll
    for (int j = 0; j < 8; j++) {
        cnt += (u[j] == t);
        if (u[j] < t) bmax = fmaxf(bmax, f[j]);
    }
    S.eqscan[tid] = cnt;
    S.bmaxs[tid] = bmax;
    __syncthreads();
    if (tid == 0) {
        unsigned int run = 0;
        for (int i = 0; i < 256; i++) { unsigned int v = S.eqscan[i]; S.eqscan[i] = run; run += v; }
        S.s_total = run;
    }
#pragma unroll
    for (int off = 128; off > 0; off >>= 1) {
        __syncthreads();
        if (tid < off) S.bmaxs[tid] = fmaxf(S.bmaxs[tid], S.bmaxs[tid + off]);
    }
    __syncthreads();

    unsigned int rank = S.eqscan[tid];
    float part = 0.0f;
#pragma unroll
    for (int j = 0; j < 8; j++) {
        bool keep;
        if (u[j] > t) keep = true;
        else if (u[j] == t) { keep = (rank < need_eq); rank++; }
        else keep = false;
        if (!keep) f[j] = 0.0f;
        part += f[j];
    }
    S.psum[tid] = part;
    __syncthreads();

    if (tid < NSTRIPE) {
        float s = 0.0f;
#pragma unroll
        for (int i = 0; i < 8; i++) s += S.psum[tid * 8 + i];
        S.ssum[tid] = s;
    }
    __syncthreads();

    if (tid == 0) {
        bool sel[NSTRIPE];
#pragma unroll
        for (int s = 0; s < NSTRIPE; s++) sel[s] = false;
        float v4 = 0.0f, v5 = 0.0f;
        for (int it = 0; it < KSTRIPE + 1; it++) {
            int best = -1; float bv = -1.0f;
            for (int s = 0; s < NSTRIPE; s++)
                if (!sel[s] && S.ssum[s] > bv) { bv = S.ssum[s]; best = s; }
            if (it < KSTRIPE) { sel[best] = true; if (it == KSTRIPE - 1) v4 = bv; }
            else v5 = bv;
        }
#pragma unroll
        for (int s = 0; s < NSTRIPE; s++) S.smask[s] = sel[s] ? 1.0f : 0.0f;

        if (flagmode) {
            float gap_n = __uint_as_float(t) - S.bmaxs[0];
            if (need_eq < S.s_total) gap_n = 0.0f;
            float gap_s = v4 - v5;
            if (gap_n < TAU1 || gap_s < TAU2) {
                int ix = atomicAdd(&g_flag_cnt, 1);
                g_flag_rows[ix] = row;
            }
        }
    }
    __syncthreads();

    // ---- emit compact (idx, val) list, deterministic index order ----
    const float sm = S.smask[tid >> 3];
    float mv[8];
    unsigned int myc = 0;
#pragma unroll
    for (int j = 0; j < 8; j++) { mv[j] = f[j] * sm; myc += (mv[j] != 0.0f); }
    S.eqscan[tid] = myc;
    __syncthreads();
    if (tid == 0) {
        unsigned int run = 0;
        for (int i = 0; i < 256; i++) { unsigned int v = S.eqscan[i]; S.eqscan[i] = run; run += v; }
        g_cnt[row] = (int)run;
    }
    __syncthreads();
    int base = (int)S.eqscan[tid];
    const int gb = row * KNEUR;
#pragma unroll
    for (int j = 0; j < 8; j++) {
        if (mv[j] != 0.0f) {
            g_idx[gb + base] = tid * 8 + j;
            g_val[gb + base] = mv[j];
            base++;
        }
    }
}

__global__ __launch_bounds__(256) void topk_flag_kernel(const float* __restrict__ C)
{
    __shared__ TopkSmem S;
    topk_body(S, C, blockIdx.x, true);
}

__global__ __launch_bounds__(256) void reset_cnt_kernel()
{
    if (threadIdx.x == 0 && blockIdx.x == 0) g_flag_cnt = 0;
}

__global__ __launch_bounds__(256) void fixup_exact_kernel(
    const float* __restrict__ h, const float* __restrict__ W2,
    const float* __restrict__ b2, float* __restrict__ c)
{
    __shared__ float hs[8][INTER];
    const int tid = threadIdx.x;
    const int nf = g_flag_cnt;

    for (int base = blockIdx.x * 8; base < nf; base += gridDim.x * 8) {
        int nrows = nf - base; if (nrows > 8) nrows = 8;
        for (int r = 0; r < nrows; r++) {
            int row = g_flag_rows[base + r];
            for (int k = tid; k < INTER; k += 256)
                hs[r][k] = h[(size_t)row * INTER + k];
        }
        __syncthreads();
#pragma unroll 1
        for (int jj = 0; jj < 8; jj++) {
            int j = tid + jj * 256;
            const float* w = W2 + (size_t)j * INTER;
            float acc[8];
#pragma unroll
            for (int r = 0; r < 8; r++) acc[r] = 0.0f;
            for (int k = 0; k < INTER; k += 4) {
                float4 w4 = *(const float4*)(w + k);
#pragma unroll
                for (int r = 0; r < 8; r++) {
                    acc[r] = fmaf(hs[r][k + 0], w4.x, acc[r]);
                    acc[r] = fmaf(hs[r][k + 1], w4.y, acc[r]);
                    acc[r] = fmaf(hs[r][k + 2], w4.z, acc[r]);
                    acc[r] = fmaf(hs[r][k + 3], w4.w, acc[r]);
                }
            }
            float bj = b2[j];
            for (int r = 0; r < nrows; r++) {
                int row = g_flag_rows[base + r];
                c[(size_t)row * CODE + j] = fmaxf(acc[r] + bj, 0.0f);
            }
        }
        __syncthreads();
    }
}

__global__ __launch_bounds__(256) void fixup_topk_kernel(const float* __restrict__ C)
{
    __shared__ TopkSmem S;
    const int nf = g_flag_cnt;
    for (int i = blockIdx.x; i < nf; i += gridDim.x) {
        topk_body(S, C, g_flag_rows[i], false);
        __syncthreads();
    }
}

// ---------------------------------------------------------------------------
// L3: sparse row-gather GEMV, exact fp32; writes d bf16 pair for L4.
// one block per row; thread owns 4 contiguous outputs.
// ---------------------------------------------------------------------------
__global__ __launch_bounds__(256) void l3_gather(
    const float* __restrict__ W3T, const float* __restrict__ b3,
    bf16* __restrict__ D0, bf16* __restrict__ D1)
{
    __shared__ float sval[KNEUR];
    __shared__ int   sidx[KNEUR];
    const int row = blockIdx.x, tid = threadIdx.x;
    const int cnt = g_cnt[row];
    if (tid < KNEUR && tid < cnt) {
        sidx[tid] = g_idx[row * KNEUR + tid];
        sval[tid] = g_val[row * KNEUR + tid];
    }
    __syncthreads();

    const int n = tid * 4;
    float4 acc = *(const float4*)(b3 + n);
    int j = 0;
    for (; j + 4 <= cnt; j += 4) {
        const float4 w0 = *(const float4*)(W3T + (size_t)sidx[j + 0] * INTER + n);
        const float4 w1 = *(const float4*)(W3T + (size_t)sidx[j + 1] * INTER + n);
        const float4 w2 = *(const float4*)(W3T + (size_t)sidx[j + 2] * INTER + n);
        const float4 w3 = *(const float4*)(W3T + (size_t)sidx[j + 3] * INTER + n);
        const float v0 = sval[j], v1 = sval[j + 1], v2 = sval[j + 2], v3 = sval[j + 3];
        acc.x = fmaf(v0, w0.x, acc.x); acc.y = fmaf(v0, w0.y, acc.y);
        acc.z = fmaf(v0, w0.z, acc.z); acc.w = fmaf(v0, w0.w, acc.w);
        acc.x = fmaf(v1, w1.x, acc.x); acc.y = fmaf(v1, w1.y, acc.y);
        acc.z = fmaf(v1, w1.z, acc.z); acc.w = fmaf(v1, w1.w, acc.w);
        acc.x = fmaf(v2, w2.x, acc.x); acc.y = fmaf(v2, w2.y, acc.y);
        acc.z = fmaf(v2, w2.z, acc.z); acc.w = fmaf(v2, w2.w, acc.w);
        acc.x = fmaf(v3, w3.x, acc.x); acc.y = fmaf(v3, w3.y, acc.y);
        acc.z = fmaf(v3, w3.z, acc.z); acc.w = fmaf(v3, w3.w, acc.w);
    }
    for (; j < cnt; j++) {
        const float4 w0 = *(const float4*)(W3T + (size_t)sidx[j] * INTER + n);
        const float v0 = sval[j];
        acc.x = fmaf(v0, w0.x, acc.x); acc.y = fmaf(v0, w0.y, acc.y);
        acc.z = fmaf(v0, w0.z, acc.z); acc.w = fmaf(v0, w0.w, acc.w);
    }

    acc.x = fmaxf(acc.x, 0.0f); acc.y = fmaxf(acc.y, 0.0f);
    acc.z = fmaxf(acc.z, 0.0f); acc.w = fmaxf(acc.w, 0.0f);

    __nv_bfloat162 p0a, p0b, p1a, p1b;
    p0a.x = __float2bfloat16(acc.x); p0a.y = __float2bfloat16(acc.y);
    p0b.x = __float2bfloat16(acc.z); p0b.y = __float2bfloat16(acc.w);
    p1a.x = __float2bfloat16(acc.x - __bfloat162float(p0a.x));
    p1a.y = __float2bfloat16(acc.y - __bfloat162float(p0a.y));
    p1b.x = __float2bfloat16(acc.z - __bfloat162float(p0b.x));
    p1b.y = __float2bfloat16(acc.w - __bfloat162float(p0b.y));
    *(__nv_bfloat162*)(D0 + (size_t)row * INTER + n)     = p0a;
    *(__nv_bfloat162*)(D0 + (size_t)row * INTER + n + 2) = p0b;
    *(__nv_bfloat162*)(D1 + (size_t)row * INTER + n)     = p1a;
    *(__nv_bfloat162*)(D1 + (size_t)row * INTER + n + 2) = p1b;
}

// ---------------------------------------------------------------------------
extern "C" void kernel_launch(void* const* d_in, const int* in_sizes, int n_in,
                              void* d_out, int out_size)
{
    const float* x  = (const float*)d_in[0];
    const float* W1 = (const float*)d_in[1];
    const float* b1 = (const float*)d_in[2];
    const float* W2 = (const float*)d_in[3];
    const float* b2 = (const float*)d_in[4];
    const float* W3 = (const float*)d_in[5];
    const float* b3 = (const float*)d_in[6];
    const float* W4 = (const float*)d_in[7];
    const float* b4 = (const float*)d_in[8];
    float* out = (float*)d_out;

    float *h, *c, *w3t;
    __half *hh16, *hl16, *w2h16, *w2l16;
    bf16 *d0, *d1, *w40, *w41;
    cudaGetSymbolAddress((void**)&h, g_h);
    cudaGetSymbolAddress((void**)&c, g_c);
    cudaGetSymbolAddress((void**)&w3t, g_w3t);
    cudaGetSymbolAddress((void**)&hh16, g_hh16);   cudaGetSymbolAddress((void**)&hl16, g_hl16);
    cudaGetSymbolAddress((void**)&w2h16, g_w2h16); cudaGetSymbolAddress((void**)&w2l16, g_w2l16);
    cudaGetSymbolAddress((void**)&d0, g_d0);       cudaGetSymbolAddress((void**)&d1, g_d1);
    cudaGetSymbolAddress((void**)&w40, g_w4_0);    cudaGetSymbolAddress((void**)&w41, g_w4_1);

    cudaFuncSetAttribute(gemm_f16c, cudaFuncAttributeMaxDynamicSharedMemorySize, SMEM_HMMA);
    cudaFuncSetAttribute(gemm_split2_f, cudaFuncAttributeMaxDynamicSharedMemorySize, SMEM_HMMA);

    auto gs = [](size_t n) { return (unsigned)((n + 255) / 256); };

    // weight prep
    split16<<<gs((size_t)CODE * INTER), 256>>>(W2, w2h16, w2l16, (size_t)CODE * INTER);
    split_pad2<<<gs((size_t)N4P * INTER), 256>>>(W4, w40, w41, IN_DIM, INTER, N4P, INTER);
    transpose_w3<<<dim3(CODE / 32, INTER / 32), dim3(32, 8)>>>(W3, w3t);

    // L1 (bit-anchor fp32) + fused h split
    sgemm_bias_relu<<<dim3(INTER / 128, BATCH / 128), 256>>>(
        x, W1, b1, h, hh16, hl16, BATCH, INTER, IN_DIM);

    // L2 fp16-split HMMA
    gemm_f16c<<<dim3(CODE / 128, BATCH / 128), 256, SMEM_HMMA>>>(
        hh16, hl16, w2h16, w2l16, b2, c);

    // topk + margins + exact fixup; emits compact lists
    reset_cnt_kernel<<<1, 32>>>();
    topk_flag_kernel<<<BATCH, 256>>>(c);
    fixup_exact_kernel<<<256, 256>>>(h, W2, b2, c);
    fixup_topk_kernel<<<512, 256>>>(c);

    // L3 sparse gather (exact fp32) -> d pair
    l3_gather<<<BATCH, 256>>>(w3t, b3, d0, d1);

    // L4 HMMA split -> out
    gemm_split2_f<<<dim3(N4P / 128, BATCH / 128), 256, SMEM_HMMA>>>(
        d0, d1, w40, w41, b4, out, INTER, IN_DIM, IN_DIM);
}